// round 2
// baseline (speedup 1.0000x reference)
#include <cuda_runtime.h>
#include <math.h>

// Problem constants
#define Bsz 2048
#define Tlen 200
#define Fdim 128
#define Hdim 256
#define Odim 6
#define G4H  (4 * Hdim)   // 1024

// ---------------------------------------------------------------------------
// Persistent device scratch (static __device__ arrays: the sanctioned
// alternative to cudaMalloc under the harness allocation guards).
// h1/h2 are ping-pong buffered: step t reads buf[t&1], writes buf[(t&1)^1].
// c1/c2/sum are read-modify-written by exactly one thread per element per
// step, so they need no double buffering.
// ---------------------------------------------------------------------------
__device__ float g_h1[2][Bsz * Hdim];
__device__ float g_c1[Bsz * Hdim];
__device__ float g_h2[2][Bsz * Hdim];
__device__ float g_c2[Bsz * Hdim];
__device__ float g_sum[Bsz * Hdim];

// Gate-interleaved weights: column (h*4 + g) holds gate g (i,j,f,o) of unit h.
// This makes each GEMM thread's 4 contiguous output columns one full LSTM
// cell, enabling a fully fused epilogue.
__device__ float g_W1r[(Fdim + Hdim) * G4H];
__device__ float g_b1r[G4H];
__device__ float g_W2r[(2 * Hdim) * G4H];
__device__ float g_b2r[G4H];

__device__ __forceinline__ float sigf(float v) {
    return 1.0f / (1.0f + expf(-v));
}

// ---------------------------------------------------------------------------
// Weight reorder: Wd[k, h*4+g] = W[k, g*H + h]  (and same for bias).
// Cheap (<1 MB moved), runs once per launch so the launch stays deterministic.
// ---------------------------------------------------------------------------
__global__ void reorder_kernel(const float* __restrict__ W,
                               const float* __restrict__ bias,
                               int K, int which)
{
    float* Wd = which ? g_W2r : g_W1r;
    float* bd = which ? g_b2r : g_b1r;
    int n = K * G4H;
    for (int idx = blockIdx.x * blockDim.x + threadIdx.x; idx < n;
         idx += gridDim.x * blockDim.x) {
        int k  = idx >> 10;        // / 1024
        int cr = idx & 1023;
        int h  = cr >> 2;
        int g  = cr & 3;
        Wd[idx] = W[k * G4H + g * Hdim + h];
        if (idx < G4H) bd[idx] = bias[g * Hdim + h];
    }
}

__global__ void zero_kernel()
{
    int idx = blockIdx.x * blockDim.x + threadIdx.x;
    if (idx < Bsz * Hdim) {
        g_h1[0][idx] = 0.0f;
        g_h2[0][idx] = 0.0f;
        g_c1[idx]    = 0.0f;
        g_c2[idx]    = 0.0f;
        g_sum[idx]   = 0.0f;
    }
}

// ---------------------------------------------------------------------------
// One LSTM layer step: Z = [seg0 | h_prev] @ Wr + br, then the TF LSTMCell
// (gates i,j,f,o, forget_bias=1) fused in the epilogue with length masking.
//
// Classic 128x128x8 fp32 SGEMM: 256 threads, 8x8 thread tile split as
// {ty*4, 64+ty*4} x {tx*4, 64+tx*4} so shared loads are float4 and
// conflict-free, and each 4-col group is one hidden unit's 4 gates.
//
// LAYER==1: seg0 = x[:, t, :]   (F=128), h_prev = h1[t&1], K=384
// LAYER==2: seg0 = h1[(t&1)^1]  (the h1 just written), h_prev = h2[t&1], K=512
// ---------------------------------------------------------------------------
template <int LAYER>
__global__ void __launch_bounds__(256, 1)
lstm_step_kernel(const float* __restrict__ x,
                 const int* __restrict__ lengths,
                 int t)
{
    constexpr int K  = (LAYER == 1) ? (Fdim + Hdim) : (2 * Hdim);
    constexpr int W0 = (LAYER == 1) ? Fdim : Hdim;   // width of first segment

    const float* __restrict__ Wd = (LAYER == 1) ? g_W1r : g_W2r;
    const float* __restrict__ bd = (LAYER == 1) ? g_b1r : g_b2r;

    const int p = t & 1;
    const float* __restrict__ hprev = (LAYER == 1) ? g_h1[p] : g_h2[p];
    const float* __restrict__ seg0  = (LAYER == 1) ? (const float*)nullptr
                                                   : g_h1[p ^ 1];
    float* __restrict__ hnext = (LAYER == 1) ? g_h1[p ^ 1] : g_h2[p ^ 1];
    float* __restrict__ cst   = (LAYER == 1) ? g_c1 : g_c2;

    __shared__ float As[8][128];
    __shared__ float Bs[8][128];

    const int tid  = threadIdx.x;
    const int tx   = tid & 15;
    const int ty   = tid >> 4;
    const int row0 = blockIdx.y * 128;   // batch offset
    const int col0 = blockIdx.x * 128;   // gate-column offset

    float acc[8][8];
#pragma unroll
    for (int i = 0; i < 8; i++)
#pragma unroll
        for (int j = 0; j < 8; j++) acc[i][j] = 0.0f;

    // A-tile load mapping: one float4 per thread (128 rows x 8 k)
    const int lr = tid >> 1;            // row within tile
    const int lk = (tid & 1) * 4;       // k quad
    // B-tile load mapping: one float4 per thread (8 k x 128 cols)
    const int bk = tid >> 5;
    const int bc = (tid & 31) * 4;

    const int gb_load = row0 + lr;
    // Hoisted row base pointers for the A-tile producer thread
    const float* __restrict__ xrow =
        (LAYER == 1) ? (x + ((long long)gb_load * Tlen + t) * Fdim) : nullptr;
    const float* __restrict__ s0row =
        (LAYER == 1) ? nullptr : (seg0 + gb_load * Hdim);
    const float* __restrict__ hprow = hprev + gb_load * Hdim;

#pragma unroll 1
    for (int k0 = 0; k0 < K; k0 += 8) {
        const int gk = k0 + lk;
        float4 av;
        if (LAYER == 1) {
            av = (gk < W0) ? *(const float4*)(xrow + gk)
                           : *(const float4*)(hprow + (gk - W0));
        } else {
            av = (gk < W0) ? *(const float4*)(s0row + gk)
                           : *(const float4*)(hprow + (gk - W0));
        }
        const float4 bv = *(const float4*)(Wd + (k0 + bk) * G4H + col0 + bc);

        __syncthreads();   // previous iteration done reading smem
        As[lk + 0][lr] = av.x;
        As[lk + 1][lr] = av.y;
        As[lk + 2][lr] = av.z;
        As[lk + 3][lr] = av.w;
        *(float4*)&Bs[bk][bc] = bv;
        __syncthreads();

#pragma unroll
        for (int kk = 0; kk < 8; kk++) {
            float a[8], b[8];
            *(float4*)&a[0] = *(const float4*)&As[kk][ty * 4];
            *(float4*)&a[4] = *(const float4*)&As[kk][64 + ty * 4];
            *(float4*)&b[0] = *(const float4*)&Bs[kk][tx * 4];
            *(float4*)&b[4] = *(const float4*)&Bs[kk][64 + tx * 4];
#pragma unroll
            for (int i = 0; i < 8; i++)
#pragma unroll
                for (int j = 0; j < 8; j++) acc[i][j] += a[i] * b[j];
        }
    }

    // Fused LSTM-cell epilogue + masking + state writeback.
    // Row indices and validity hoisted out of the column loop.
    int  gbv[8];
    bool val[8];
#pragma unroll
    for (int i = 0; i < 8; i++) {
        gbv[i] = row0 + ((i < 4) ? (ty * 4 + i) : (64 + ty * 4 + (i - 4)));
        val[i] = (t < lengths[gbv[i]]);
    }

#pragma unroll
    for (int i = 0; i < 8; i++) {
        const int gb = gbv[i];
#pragma unroll
        for (int cg = 0; cg < 2; cg++) {
            const int cbase = col0 + cg * 64 + tx * 4;  // 4-aligned: one unit
            const int h   = cbase >> 2;
            const int idx = gb * Hdim + h;
            if (val[i]) {
                const float zi = acc[i][cg * 4 + 0] + bd[cbase + 0];
                const float zj = acc[i][cg * 4 + 1] + bd[cbase + 1];
                const float zf = acc[i][cg * 4 + 2] + bd[cbase + 2];
                const float zo = acc[i][cg * 4 + 3] + bd[cbase + 3];
                const float cold = cst[idx];
                const float nc = cold * sigf(zf + 1.0f) + sigf(zi) * tanhf(zj);
                const float nh = tanhf(nc) * sigf(zo);
                cst[idx]   = nc;
                hnext[idx] = nh;
                if (LAYER == 2) g_sum[idx] += nh;
            } else {
                // past sequence end: state copied through, no output
                hnext[idx] = hprev[idx];
            }
        }
    }
}

// ---------------------------------------------------------------------------
// logits[b,o] = dot(sum[b,:], Wout[:,o]) / lengths[b] + bout[o]
// Tiny (2048x6, K=256): one thread per output element.
// ---------------------------------------------------------------------------
__global__ void final_kernel(const int* __restrict__ lengths,
                             const float* __restrict__ Wout,
                             const float* __restrict__ bout,
                             float* __restrict__ out)
{
    const int idx = blockIdx.x * blockDim.x + threadIdx.x;
    if (idx >= Bsz * Odim) return;
    const int b = idx / Odim;
    const int o = idx % Odim;
    const float* s = g_sum + b * Hdim;
    float acc = 0.0f;
#pragma unroll 8
    for (int h = 0; h < Hdim; h++) acc += s[h] * Wout[h * Odim + o];
    out[idx] = acc / (float)lengths[b] + bout[o];
}

// ---------------------------------------------------------------------------
// Inputs (metadata order): x, lengths, W1, b1, W2, b2, Wout, bout
// ---------------------------------------------------------------------------
extern "C" void kernel_launch(void* const* d_in, const int* in_sizes, int n_in,
                              void* d_out, int out_size)
{
    const float* x       = (const float*)d_in[0];
    const int*   lengths = (const int*)d_in[1];
    const float* W1      = (const float*)d_in[2];
    const float* b1      = (const float*)d_in[3];
    const float* W2      = (const float*)d_in[4];
    const float* b2      = (const float*)d_in[5];
    const float* Wout    = (const float*)d_in[6];
    const float* bout    = (const float*)d_in[7];
    float* out = (float*)d_out;

    reorder_kernel<<<1536, 256>>>(W1, b1, Fdim + Hdim, 0);
    reorder_kernel<<<2048, 256>>>(W2, b2, 2 * Hdim, 1);
    zero_kernel<<<(Bsz * Hdim) / 256, 256>>>();

    dim3 grid(G4H / 128, Bsz / 128);   // (8, 16) = 128 blocks
    for (int t = 0; t < Tlen; t++) {
        lstm_step_kernel<1><<<grid, 256>>>(x, lengths, t);
        lstm_step_kernel<2><<<grid, 256>>>(x, lengths, t);
    }

    final_kernel<<<(Bsz * Odim + 255) / 256, 256>>>(lengths, Wout, bout, out);
}

// round 3
// speedup vs baseline: 1.3354x; 1.3354x over previous
#include <cuda_runtime.h>
#include <math.h>
#include <stdint.h>

// Problem constants
#define Bsz  2048
#define Tlen 200
#define Fdim 128
#define Hdim 256
#define Odim 6
#define G4H  (4 * Hdim)   // 1024

// ---------------------------------------------------------------------------
// Persistent device scratch (static __device__ arrays — no cudaMalloc).
// h1/h2 ping-pong: step t reads buf[t&1], writes buf[(t&1)^1].
// ---------------------------------------------------------------------------
__device__ float g_h1[2][Bsz * Hdim];
__device__ float g_c1[Bsz * Hdim];
__device__ float g_h2[2][Bsz * Hdim];
__device__ float g_c2[Bsz * Hdim];
__device__ float g_sum[Bsz * Hdim];

// Gate-interleaved + tf32 hi/lo pre-split weights.
// Column (h*4+g) = gate g (i,j,f,o) of hidden unit h.
__device__ float g_W1hi[(Fdim + Hdim) * G4H];
__device__ float g_W1lo[(Fdim + Hdim) * G4H];
__device__ float g_W2hi[(2 * Hdim) * G4H];
__device__ float g_W2lo[(2 * Hdim) * G4H];
__device__ float g_b1r[G4H];
__device__ float g_b2r[G4H];

// ---------------------------------------------------------------------------
// tf32 helpers
// ---------------------------------------------------------------------------
__device__ __forceinline__ void split_tf32(float a, uint32_t& hi, uint32_t& lo) {
    asm("cvt.rna.tf32.f32 %0, %1;" : "=r"(hi) : "f"(a));
    float l = a - __uint_as_float(hi);   // exact (Dekker split)
    asm("cvt.rna.tf32.f32 %0, %1;" : "=r"(lo) : "f"(l));
}

__device__ __forceinline__ void mma_tf32(float* c, const uint32_t* a, const uint32_t* b) {
    asm volatile(
        "mma.sync.aligned.m16n8k8.row.col.f32.tf32.tf32.f32 "
        "{%0,%1,%2,%3}, {%4,%5,%6,%7}, {%8,%9}, {%0,%1,%2,%3};"
        : "+f"(c[0]), "+f"(c[1]), "+f"(c[2]), "+f"(c[3])
        : "r"(a[0]), "r"(a[1]), "r"(a[2]), "r"(a[3]), "r"(b[0]), "r"(b[1]));
}

#define CPASYNC16(dst_u32, src_ptr) \
    asm volatile("cp.async.ca.shared.global [%0], [%1], 16;" :: "r"(dst_u32), "l"(src_ptr))
#define CP_COMMIT() asm volatile("cp.async.commit_group;")
#define CP_WAIT1()  asm volatile("cp.async.wait_group 1;")

__device__ __forceinline__ float fast_sig(float v) {
    return 1.0f / (1.0f + __expf(-v));
}
__device__ __forceinline__ float fast_tanh(float v) {
    // tanh(x) = 1 - 2/(e^{2x}+1); __expf saturates cleanly for large |x|
    return 1.0f - 2.0f / (__expf(2.0f * v) + 1.0f);
}

// ---------------------------------------------------------------------------
// Weight reorder + tf32 hi/lo split (runs once per launch; <8 MB moved).
// Whi/Wlo[k, h*4+g] from W[k, g*H+h].
// ---------------------------------------------------------------------------
__global__ void reorder_kernel(const float* __restrict__ W,
                               const float* __restrict__ bias,
                               int K, int which)
{
    float* Whi = which ? g_W2hi : g_W1hi;
    float* Wlo = which ? g_W2lo : g_W1lo;
    float* bd  = which ? g_b2r  : g_b1r;
    int n = K * G4H;
    for (int idx = blockIdx.x * blockDim.x + threadIdx.x; idx < n;
         idx += gridDim.x * blockDim.x) {
        int k  = idx >> 10;
        int cr = idx & 1023;
        int h  = cr >> 2;
        int g  = cr & 3;
        float w = W[k * G4H + g * Hdim + h];
        uint32_t hi, lo;
        split_tf32(w, hi, lo);
        Whi[idx] = __uint_as_float(hi);
        Wlo[idx] = __uint_as_float(lo);
        if (idx < G4H) bd[idx] = bias[g * Hdim + h];
    }
}

__global__ void zero_kernel()
{
    int idx = blockIdx.x * blockDim.x + threadIdx.x;
    if (idx < Bsz * Hdim) {
        g_h1[0][idx] = 0.0f;
        g_h2[0][idx] = 0.0f;
        g_c1[idx]    = 0.0f;
        g_c2[idx]    = 0.0f;
        g_sum[idx]   = 0.0f;
    }
}

// ---------------------------------------------------------------------------
// Tensor-core LSTM step.
// Block tile: 128 batch rows x 128 gate cols. 256 threads = 8 warps (4 row x
// 2 col), warp tile 32x64 -> 2 m16 x 8 n8 mma tiles. K chunked by 32, cp.async
// double-buffered. 3xTF32 split for fp32-grade accuracy. Smem strides 36/136
// make all fragment LDS conflict-free. Epilogue stages Z in smem, then each
// thread owns full (row, unit) cells: bias + TF LSTMCell + masking + state
// writeback fused.
//
// LAYER 1: A = [x_t | h1_prev], K=384.  LAYER 2: A = [h1_new | h2_prev], K=512.
// ---------------------------------------------------------------------------
#define AS_STRIDE 36
#define BS_STRIDE 136
#define ZS_STRIDE 132
#define A_TILE   (128 * AS_STRIDE)            // 4608 floats
#define B_TILE   (32 * BS_STRIDE)             // 4352 floats
#define STG_SZ   (A_TILE + 2 * B_TILE)        // 13312 floats per stage
#define SMEM_FLOATS (2 * STG_SZ)              // 26624 floats = 106496 B

template <int LAYER>
__global__ void __launch_bounds__(256, 1)
lstm_step_mma(const float* __restrict__ x,
              const int* __restrict__ lengths,
              int t)
{
    constexpr int K  = (LAYER == 1) ? (Fdim + Hdim) : (2 * Hdim);
    constexpr int W0 = (LAYER == 1) ? Fdim : Hdim;
    constexpr int NC = K / 32;

    extern __shared__ float sm[];
    const uint32_t smb = (uint32_t)__cvta_generic_to_shared(sm);

    const float* __restrict__ Whi  = (LAYER == 1) ? g_W1hi : g_W2hi;
    const float* __restrict__ Wlo  = (LAYER == 1) ? g_W1lo : g_W2lo;
    const float* __restrict__ bias = (LAYER == 1) ? g_b1r  : g_b2r;

    const int p = t & 1;
    const float* __restrict__ hprev = (LAYER == 1) ? g_h1[p] : g_h2[p];
    float* __restrict__ hnext = (LAYER == 1) ? g_h1[p ^ 1] : g_h2[p ^ 1];
    float* __restrict__ cst   = (LAYER == 1) ? g_c1 : g_c2;

    const int tid  = threadIdx.x;
    const int col0 = blockIdx.x * 128;   // gate-column base
    const int row0 = blockIdx.y * 128;   // batch base

    // ---- producer mappings ----
    const int arow = tid >> 1;            // 0..127
    const int aks  = (tid & 1) * 16;      // k sub-offset 0 or 16
    const int bk   = tid >> 3;            // 0..31 (k row of B tile)
    const int bm   = (tid & 7) * 4;       // col sub-offset

    const long arow_g = row0 + arow;
    const float* pA0 = (LAYER == 1)
        ? (x + (arow_g * Tlen + t) * Fdim)       // x_t row
        : (g_h1[p ^ 1] + arow_g * Hdim);         // h1 just written
    const float* pA1 = hprev + arow_g * Hdim;    // this layer's own h_prev

    const float* pWh = Whi + col0 + bm;
    const float* pWl = Wlo + col0 + bm;

    auto issue_chunk = [&](int s, int k0) {
        // A tile: 4 x 16B per thread
        uint32_t asb = smb + (uint32_t)(s * STG_SZ + arow * AS_STRIDE + aks) * 4u;
#pragma unroll
        for (int i = 0; i < 4; i++) {
            int gk = k0 + aks + 4 * i;
            const float* src = (gk < W0) ? (pA0 + gk) : (pA1 + (gk - W0));
            CPASYNC16(asb + 16u * i, src);
        }
        // B hi/lo tiles: 4+4 x 16B per thread
        uint32_t bhb = smb + (uint32_t)(s * STG_SZ + A_TILE + bk * BS_STRIDE + bm) * 4u;
        uint32_t blb = bhb + (uint32_t)B_TILE * 4u;
        const float* wh = pWh + (long)(k0 + bk) * G4H;
        const float* wl = pWl + (long)(k0 + bk) * G4H;
#pragma unroll
        for (int j = 0; j < 4; j++) {
            CPASYNC16(bhb + 128u * j, wh + 32 * j);
            CPASYNC16(blb + 128u * j, wl + 32 * j);
        }
    };

    // ---- consumer mappings ----
    const int lane = tid & 31;
    const int gq   = lane >> 2;   // group 0..7
    const int rq   = lane & 3;    // thread-in-group 0..3
    const int wid  = tid >> 5;
    const int wr   = wid & 3;     // warp row 0..3 (32 rows each)
    const int wc   = wid >> 2;    // warp col 0..1 (64 cols each)

    float acc[2][8][4];
#pragma unroll
    for (int mt = 0; mt < 2; mt++)
#pragma unroll
        for (int nt = 0; nt < 8; nt++)
#pragma unroll
            for (int q = 0; q < 4; q++) acc[mt][nt][q] = 0.0f;

    // ---- pipelined main loop ----
    issue_chunk(0, 0);
    CP_COMMIT();

#pragma unroll 1
    for (int c = 0; c < NC; c++) {
        if (c + 1 < NC) issue_chunk((c + 1) & 1, (c + 1) * 32);
        CP_COMMIT();     // commit (possibly empty) group to keep counts uniform
        CP_WAIT1();      // chunk c has landed
        __syncthreads();

        const float* as = sm + (c & 1) * STG_SZ;
        const float* bh = as + A_TILE;
        const float* bl = bh + B_TILE;

#pragma unroll
        for (int ks = 0; ks < 4; ks++) {
            const int kk = ks * 8 + rq;

            uint32_t ahi[2][4], alo[2][4];
#pragma unroll
            for (int mt = 0; mt < 2; mt++) {
                const int rr = wr * 32 + mt * 16 + gq;
                split_tf32(as[rr * AS_STRIDE + kk],            ahi[mt][0], alo[mt][0]);
                split_tf32(as[(rr + 8) * AS_STRIDE + kk],      ahi[mt][1], alo[mt][1]);
                split_tf32(as[rr * AS_STRIDE + kk + 4],        ahi[mt][2], alo[mt][2]);
                split_tf32(as[(rr + 8) * AS_STRIDE + kk + 4],  ahi[mt][3], alo[mt][3]);
            }

            uint32_t bhiR[8][2], bloR[8][2];
#pragma unroll
            for (int nt = 0; nt < 8; nt++) {
                const int nb = wc * 64 + nt * 8 + gq;
                bhiR[nt][0] = __float_as_uint(bh[kk * BS_STRIDE + nb]);
                bhiR[nt][1] = __float_as_uint(bh[(kk + 4) * BS_STRIDE + nb]);
                bloR[nt][0] = __float_as_uint(bl[kk * BS_STRIDE + nb]);
                bloR[nt][1] = __float_as_uint(bl[(kk + 4) * BS_STRIDE + nb]);
            }

#pragma unroll
            for (int mt = 0; mt < 2; mt++)
#pragma unroll
                for (int nt = 0; nt < 8; nt++) {
                    mma_tf32(acc[mt][nt], ahi[mt], bhiR[nt]);
                    mma_tf32(acc[mt][nt], ahi[mt], bloR[nt]);
                    mma_tf32(acc[mt][nt], alo[mt], bhiR[nt]);
                }
        }
        __syncthreads();   // protect buffer reuse by next issue
    }

    // ---- stage Z into smem (reuses pipeline buffers) ----
    float* Zs = sm;
#pragma unroll
    for (int mt = 0; mt < 2; mt++)
#pragma unroll
        for (int nt = 0; nt < 8; nt++) {
            const int row = wr * 32 + mt * 16 + gq;
            const int col = wc * 64 + nt * 8 + 2 * rq;
            Zs[row * ZS_STRIDE + col]           = acc[mt][nt][0];
            Zs[row * ZS_STRIDE + col + 1]       = acc[mt][nt][1];
            Zs[(row + 8) * ZS_STRIDE + col]     = acc[mt][nt][2];
            Zs[(row + 8) * ZS_STRIDE + col + 1] = acc[mt][nt][3];
        }
    __syncthreads();

    // ---- fused LSTM cell: each thread owns 1 row x 16 units ----
    {
        const int row  = tid >> 1;                // 0..127
        const int ub   = (tid & 1) * 16;          // unit sub-base
        const int rowg = row0 + row;
        const bool valid = (t < lengths[rowg]);
        const int ubase = (col0 >> 2) + ub;       // global unit base

#pragma unroll 4
        for (int u = 0; u < 16; u++) {
            const int n4  = (ub + u) * 4;
            const int idx = rowg * Hdim + ubase + u;
            if (valid) {
                float4 z = *(const float4*)&Zs[row * ZS_STRIDE + n4];
                float4 bv = *(const float4*)&bias[col0 + n4];
                const float zi = z.x + bv.x;
                const float zj = z.y + bv.y;
                const float zf = z.z + bv.z;
                const float zo = z.w + bv.w;
                const float nc = cst[idx] * fast_sig(zf + 1.0f)
                               + fast_sig(zi) * fast_tanh(zj);
                const float nh = fast_tanh(nc) * fast_sig(zo);
                cst[idx]   = nc;
                hnext[idx] = nh;
                if (LAYER == 2) g_sum[idx] += nh;
            } else {
                hnext[idx] = hprev[idx];
            }
        }
    }
}

// ---------------------------------------------------------------------------
// logits[b,o] = dot(sum[b,:], Wout[:,o]) / lengths[b] + bout[o]
// ---------------------------------------------------------------------------
__global__ void final_kernel(const int* __restrict__ lengths,
                             const float* __restrict__ Wout,
                             const float* __restrict__ bout,
                             float* __restrict__ out)
{
    const int idx = blockIdx.x * blockDim.x + threadIdx.x;
    if (idx >= Bsz * Odim) return;
    const int b = idx / Odim;
    const int o = idx % Odim;
    const float* s = g_sum + b * Hdim;
    float acc = 0.0f;
#pragma unroll 8
    for (int h = 0; h < Hdim; h++) acc += s[h] * Wout[h * Odim + o];
    out[idx] = acc / (float)lengths[b] + bout[o];
}

// ---------------------------------------------------------------------------
// Inputs (metadata order): x, lengths, W1, b1, W2, b2, Wout, bout
// ---------------------------------------------------------------------------
extern "C" void kernel_launch(void* const* d_in, const int* in_sizes, int n_in,
                              void* d_out, int out_size)
{
    const float* x       = (const float*)d_in[0];
    const int*   lengths = (const int*)d_in[1];
    const float* W1      = (const float*)d_in[2];
    const float* b1      = (const float*)d_in[3];
    const float* W2      = (const float*)d_in[4];
    const float* b2      = (const float*)d_in[5];
    const float* Wout    = (const float*)d_in[6];
    const float* bout    = (const float*)d_in[7];
    float* out = (float*)d_out;

    const int smem_bytes = SMEM_FLOATS * 4;  // 106496
    cudaFuncSetAttribute(lstm_step_mma<1>,
                         cudaFuncAttributeMaxDynamicSharedMemorySize, smem_bytes);
    cudaFuncSetAttribute(lstm_step_mma<2>,
                         cudaFuncAttributeMaxDynamicSharedMemorySize, smem_bytes);

    reorder_kernel<<<1536, 256>>>(W1, b1, Fdim + Hdim, 0);
    reorder_kernel<<<2048, 256>>>(W2, b2, 2 * Hdim, 1);
    zero_kernel<<<(Bsz * Hdim) / 256, 256>>>();

    dim3 grid(G4H / 128, Bsz / 128);   // (8, 16) = 128 blocks
    for (int t = 0; t < Tlen; t++) {
        lstm_step_mma<1><<<grid, 256, smem_bytes>>>(x, lengths, t);
        lstm_step_mma<2><<<grid, 256, smem_bytes>>>(x, lengths, t);
    }

    final_kernel<<<(Bsz * Odim + 255) / 256, 256>>>(lengths, Wout, bout, out);
}

// round 4
// speedup vs baseline: 1.3561x; 1.0155x over previous
#include <cuda_runtime.h>
#include <math.h>
#include <stdint.h>

// Problem constants
#define Bsz  2048
#define Tlen 200
#define Fdim 128
#define Hdim 256
#define Odim 6
#define G4H  (4 * Hdim)   // 1024

#define NC1 12            // K/32 for layer 1 (K=384)
#define NC2 16            // K/32 for layer 2 (K=512)

// ---------------------------------------------------------------------------
// Persistent device scratch (static __device__ arrays — no cudaMalloc).
// h1/h2 ping-pong: step t reads buf[t&1], writes buf[(t&1)^1].
// ---------------------------------------------------------------------------
__device__ float g_h1[2][Bsz * Hdim];
__device__ float g_c1[Bsz * Hdim];
__device__ float g_h2[2][Bsz * Hdim];
__device__ float g_c2[Bsz * Hdim];
__device__ float g_sum[Bsz * Hdim];

// Fragment-ordered, gate-interleaved, tf32 hi/lo pre-split weights.
// Layout: idx = ((((s*NC + c)*4 + ks)*4 + q)*32 + lane)*4 + nt
//   s  = 32-col strip (0..31), c = k-chunk (32 wide), ks = k-substep (8 wide)
//   q  = {0: hi reg0, 1: hi reg1, 2: lo reg0, 3: lo reg1}, lane = mma lane
//   nt = n8-tile within strip (0..3)
// So one lane's 4 nt-fragments are one contiguous float4.
__device__ float g_W1f[32 * NC1 * 2048];
__device__ float g_W2f[32 * NC2 * 2048];
__device__ float g_b1r[G4H];
__device__ float g_b2r[G4H];

// ---------------------------------------------------------------------------
// tf32 helpers
// ---------------------------------------------------------------------------
__device__ __forceinline__ void split_tf32(float a, uint32_t& hi, uint32_t& lo) {
    asm("cvt.rna.tf32.f32 %0, %1;" : "=r"(hi) : "f"(a));
    float l = a - __uint_as_float(hi);   // exact (Dekker split)
    asm("cvt.rna.tf32.f32 %0, %1;" : "=r"(lo) : "f"(l));
}

__device__ __forceinline__ void mma_tf32(float* c, const uint32_t* a, const uint32_t* b) {
    asm volatile(
        "mma.sync.aligned.m16n8k8.row.col.f32.tf32.tf32.f32 "
        "{%0,%1,%2,%3}, {%4,%5,%6,%7}, {%8,%9}, {%0,%1,%2,%3};"
        : "+f"(c[0]), "+f"(c[1]), "+f"(c[2]), "+f"(c[3])
        : "r"(a[0]), "r"(a[1]), "r"(a[2]), "r"(a[3]), "r"(b[0]), "r"(b[1]));
}

#define CPASYNC16(dst_u32, src_ptr) \
    asm volatile("cp.async.ca.shared.global [%0], [%1], 16;" :: "r"(dst_u32), "l"(src_ptr))
#define CP_COMMIT() asm volatile("cp.async.commit_group;")
#define CP_WAIT1()  asm volatile("cp.async.wait_group 1;")

__device__ __forceinline__ float fast_sig(float v) {
    return 1.0f / (1.0f + __expf(-v));
}
__device__ __forceinline__ float fast_tanh(float v) {
    return 1.0f - 2.0f / (__expf(2.0f * v) + 1.0f);
}

// ---------------------------------------------------------------------------
// Weight reorder into fragment order + tf32 hi/lo split (once per launch).
// Source W is [K, 4H] with column g*H+h; we map gate-col (h*4+g).
// ---------------------------------------------------------------------------
__global__ void reorder_frag(const float* __restrict__ W,
                             const float* __restrict__ bias,
                             int NC, int which)
{
    float* Wf = which ? g_W2f : g_W1f;
    float* bd = which ? g_b2r : g_b1r;
    const int n = 32 * NC * 2048;
    for (int idx = blockIdx.x * blockDim.x + threadIdx.x; idx < n;
         idx += gridDim.x * blockDim.x) {
        int nt   = idx & 3;
        int tmp  = idx >> 2;
        int lane = tmp & 31;  tmp >>= 5;
        int q    = tmp & 3;   tmp >>= 2;
        int ks   = tmp & 3;   tmp >>= 2;
        int c    = tmp % NC;
        int s    = tmp / NC;

        int r    = q & 1;       // b-register index (k or k+4)
        int isLo = q >> 1;
        int gcol = s * 32 + nt * 8 + (lane >> 2);   // gate-interleaved col
        int k    = c * 32 + ks * 8 + (lane & 3) + r * 4;

        int h = gcol >> 2;
        int g = gcol & 3;
        float w = W[k * G4H + g * Hdim + h];
        uint32_t hi, lo;
        split_tf32(w, hi, lo);
        Wf[idx] = __uint_as_float(isLo ? lo : hi);

        if (idx < G4H) {
            int hh = idx >> 2, gg = idx & 3;
            bd[idx] = bias[gg * Hdim + hh];
        }
    }
}

__global__ void zero_kernel()
{
    int idx = blockIdx.x * blockDim.x + threadIdx.x;
    if (idx < Bsz * Hdim) {
        g_h1[0][idx] = 0.0f;
        g_h2[0][idx] = 0.0f;
        g_c1[idx]    = 0.0f;
        g_c2[idx]    = 0.0f;
        g_sum[idx]   = 0.0f;
    }
}

// ---------------------------------------------------------------------------
// Tensor-core LSTM step, v2.
// Block: 128 batch rows x 128 gate cols, 512 threads = 16 warps (4 row x 4
// col), warp tile 32x32 (2 m16 x 4 n8). K chunked by 32, cp.async double
// buffered. B comes from fragment-ordered gmem (L2-resident) -> smem ->
// 4 conflict-free LDS.128 per k-substep. A split to 3xTF32 in registers.
// Epilogue: Z staged in smem, then full TF LSTMCell + masking fused.
// ---------------------------------------------------------------------------
#define AS_STRIDE 36
#define A_TILE (128 * AS_STRIDE)   // 4608 floats
#define B_TILE 8192                // 4 strips * 2048 floats
#define STG_SZ (A_TILE + B_TILE)   // 12800 floats per stage
#define SMEM_FLOATS (2 * STG_SZ)   // 25600 floats = 102400 B
#define ZS_STRIDE 132

template <int LAYER>
__global__ void __launch_bounds__(512, 1)
lstm_step_mma(const float* __restrict__ x,
              const int* __restrict__ lengths,
              int t)
{
    constexpr int K  = (LAYER == 1) ? (Fdim + Hdim) : (2 * Hdim);
    constexpr int W0 = (LAYER == 1) ? Fdim : Hdim;
    constexpr int NC = K / 32;

    extern __shared__ float sm[];
    const uint32_t smb = (uint32_t)__cvta_generic_to_shared(sm);

    const float* __restrict__ Wf   = (LAYER == 1) ? g_W1f : g_W2f;
    const float* __restrict__ bias = (LAYER == 1) ? g_b1r : g_b2r;

    const int p = t & 1;
    const float* __restrict__ hprev = (LAYER == 1) ? g_h1[p] : g_h2[p];
    float* __restrict__ hnext = (LAYER == 1) ? g_h1[p ^ 1] : g_h2[p ^ 1];
    float* __restrict__ cst   = (LAYER == 1) ? g_c1 : g_c2;

    const int tid  = threadIdx.x;
    const int col0 = blockIdx.x * 128;
    const int row0 = blockIdx.y * 128;
    const int s0   = blockIdx.x * 4;    // strip base for this CTA

    // ---- producer mappings ----
    const int arow = tid >> 2;          // 0..127
    const int aks  = (tid & 3) * 8;     // k sub-offset within chunk

    const long arow_g = row0 + arow;
    const float* pA0 = (LAYER == 1)
        ? (x + (arow_g * Tlen + t) * Fdim)
        : (g_h1[p ^ 1] + arow_g * Hdim);
    const float* pA1 = hprev + arow_g * Hdim;

    auto issue_chunk = [&](int s, int c) {
        const int k0 = c * 32;
        // A: 2 x float4 per thread
        uint32_t ab = smb + (uint32_t)(s * STG_SZ + arow * AS_STRIDE + aks) * 4u;
        {
            int gk = k0 + aks;
            const float* src = (gk < W0) ? (pA0 + gk) : (pA1 + (gk - W0));
            CPASYNC16(ab, src);
            gk += 4;
            src = (gk < W0) ? (pA0 + gk) : (pA1 + (gk - W0));
            CPASYNC16(ab + 16u, src);
        }
        // B fragments: 4 x float4 per thread (strip j = 0..3)
#pragma unroll
        for (int j = 0; j < 4; j++) {
            const float* src = Wf + (long)((s0 + j) * NC + c) * 2048 + tid * 4;
            uint32_t dst = smb +
                (uint32_t)(s * STG_SZ + A_TILE + j * 2048 + tid * 4) * 4u;
            CPASYNC16(dst, src);
        }
    };

    // ---- consumer mappings ----
    const int lane = tid & 31;
    const int gq   = lane >> 2;
    const int rq   = lane & 3;
    const int wid  = tid >> 5;
    const int wr   = wid & 3;      // warp row (32 rows)
    const int wcol = wid >> 2;     // warp col strip (32 cols)

    float acc[2][4][4];
#pragma unroll
    for (int mt = 0; mt < 2; mt++)
#pragma unroll
        for (int nt = 0; nt < 4; nt++)
#pragma unroll
            for (int q = 0; q < 4; q++) acc[mt][nt][q] = 0.0f;

    issue_chunk(0, 0);
    CP_COMMIT();

#pragma unroll 1
    for (int c = 0; c < NC; c++) {
        if (c + 1 < NC) issue_chunk((c + 1) & 1, c + 1);
        CP_COMMIT();
        CP_WAIT1();
        __syncthreads();

        const float* as = sm + (c & 1) * STG_SZ;
        const float* bs = as + A_TILE + wcol * 2048;

#pragma unroll
        for (int ks = 0; ks < 4; ks++) {
            const int kk = ks * 8 + rq;

            // B fragments: 4 conflict-free LDS.128
            float h0[4], h1[4], l0[4], l1[4];
            *(float4*)h0 = *(const float4*)&bs[(ks * 4 + 0) * 128 + lane * 4];
            *(float4*)h1 = *(const float4*)&bs[(ks * 4 + 1) * 128 + lane * 4];
            *(float4*)l0 = *(const float4*)&bs[(ks * 4 + 2) * 128 + lane * 4];
            *(float4*)l1 = *(const float4*)&bs[(ks * 4 + 3) * 128 + lane * 4];

            // A fragments: scalar LDS + in-register split
            uint32_t ahi[2][4], alo[2][4];
#pragma unroll
            for (int mt = 0; mt < 2; mt++) {
                const int rr = wr * 32 + mt * 16 + gq;
                split_tf32(as[rr * AS_STRIDE + kk],           ahi[mt][0], alo[mt][0]);
                split_tf32(as[(rr + 8) * AS_STRIDE + kk],     ahi[mt][1], alo[mt][1]);
                split_tf32(as[rr * AS_STRIDE + kk + 4],       ahi[mt][2], alo[mt][2]);
                split_tf32(as[(rr + 8) * AS_STRIDE + kk + 4], ahi[mt][3], alo[mt][3]);
            }

#pragma unroll
            for (int mt = 0; mt < 2; mt++)
#pragma unroll
                for (int nt = 0; nt < 4; nt++) {
                    uint32_t bh[2] = { __float_as_uint(h0[nt]), __float_as_uint(h1[nt]) };
                    uint32_t bl[2] = { __float_as_uint(l0[nt]), __float_as_uint(l1[nt]) };
                    mma_tf32(acc[mt][nt], ahi[mt], bh);
                    mma_tf32(acc[mt][nt], ahi[mt], bl);
                    mma_tf32(acc[mt][nt], alo[mt], bh);
                }
        }
        __syncthreads();
    }

    // ---- stage Z in smem ----
    float* Zs = sm;
#pragma unroll
    for (int mt = 0; mt < 2; mt++)
#pragma unroll
        for (int nt = 0; nt < 4; nt++) {
            const int row = wr * 32 + mt * 16 + gq;
            const int col = wcol * 32 + nt * 8 + 2 * rq;
            Zs[row * ZS_STRIDE + col]           = acc[mt][nt][0];
            Zs[row * ZS_STRIDE + col + 1]       = acc[mt][nt][1];
            Zs[(row + 8) * ZS_STRIDE + col]     = acc[mt][nt][2];
            Zs[(row + 8) * ZS_STRIDE + col + 1] = acc[mt][nt][3];
        }
    __syncthreads();

    // ---- fused LSTM cell: thread = 1 row x 8 units ----
    {
        const int row  = tid >> 2;
        const int ub   = (tid & 3) * 8;
        const int rowg = row0 + row;
        const bool valid = (t < lengths[rowg]);
        const int ubase = (col0 >> 2) + ub;

#pragma unroll 4
        for (int u = 0; u < 8; u++) {
            const int n4  = (ub + u) * 4;
            const int idx = rowg * Hdim + ubase + u;
            if (valid) {
                float4 z  = *(const float4*)&Zs[row * ZS_STRIDE + n4];
                float4 bv = *(const float4*)&bias[col0 + n4];
                const float zi = z.x + bv.x;
                const float zj = z.y + bv.y;
                const float zf = z.z + bv.z;
                const float zo = z.w + bv.w;
                const float nc = cst[idx] * fast_sig(zf + 1.0f)
                               + fast_sig(zi) * fast_tanh(zj);
                const float nh = fast_tanh(nc) * fast_sig(zo);
                cst[idx]   = nc;
                hnext[idx] = nh;
                if (LAYER == 2) g_sum[idx] += nh;
            } else {
                hnext[idx] = hprev[idx];
            }
        }
    }
}

// ---------------------------------------------------------------------------
// logits[b,o] = dot(sum[b,:], Wout[:,o]) / lengths[b] + bout[o]
// ---------------------------------------------------------------------------
__global__ void final_kernel(const int* __restrict__ lengths,
                             const float* __restrict__ Wout,
                             const float* __restrict__ bout,
                             float* __restrict__ out)
{
    const int idx = blockIdx.x * blockDim.x + threadIdx.x;
    if (idx >= Bsz * Odim) return;
    const int b = idx / Odim;
    const int o = idx % Odim;
    const float* s = g_sum + b * Hdim;
    float acc = 0.0f;
#pragma unroll 8
    for (int h = 0; h < Hdim; h++) acc += s[h] * Wout[h * Odim + o];
    out[idx] = acc / (float)lengths[b] + bout[o];
}

// ---------------------------------------------------------------------------
// Inputs (metadata order): x, lengths, W1, b1, W2, b2, Wout, bout
// ---------------------------------------------------------------------------
extern "C" void kernel_launch(void* const* d_in, const int* in_sizes, int n_in,
                              void* d_out, int out_size)
{
    const float* x       = (const float*)d_in[0];
    const int*   lengths = (const int*)d_in[1];
    const float* W1      = (const float*)d_in[2];
    const float* b1      = (const float*)d_in[3];
    const float* W2      = (const float*)d_in[4];
    const float* b2      = (const float*)d_in[5];
    const float* Wout    = (const float*)d_in[6];
    const float* bout    = (const float*)d_in[7];
    float* out = (float*)d_out;

    const int smem_bytes = SMEM_FLOATS * 4;   // 102400
    cudaFuncSetAttribute(lstm_step_mma<1>,
                         cudaFuncAttributeMaxDynamicSharedMemorySize, smem_bytes);
    cudaFuncSetAttribute(lstm_step_mma<2>,
                         cudaFuncAttributeMaxDynamicSharedMemorySize, smem_bytes);

    reorder_frag<<<2048, 256>>>(W1, b1, NC1, 0);
    reorder_frag<<<2048, 256>>>(W2, b2, NC2, 1);
    zero_kernel<<<(Bsz * Hdim) / 256, 256>>>();

    dim3 grid(G4H / 128, Bsz / 128);   // (8, 16) = 128 blocks
    for (int t = 0; t < Tlen; t++) {
        lstm_step_mma<1><<<grid, 512, smem_bytes>>>(x, lengths, t);
        lstm_step_mma<2><<<grid, 512, smem_bytes>>>(x, lengths, t);
    }

    final_kernel<<<(Bsz * Odim + 255) / 256, 256>>>(lengths, Wout, bout, out);
}

// round 6
// speedup vs baseline: 2.1651x; 1.5966x over previous
#include <cuda_runtime.h>
#include <cuda_bf16.h>
#include <math.h>
#include <stdint.h>

// Problem constants
#define Bsz  2048
#define Tlen 200
#define Fdim 128
#define Hdim 256
#define Odim 6
#define G4H  1024
#define KC   32
#define NC1  12          // 384/32
#define NC2  16          // 512/32
#define HW   (Hdim / 2)  // packed bf16x2 words per h row  (128)
#define XW   (Fdim / 2)  // packed words per x row          (64)
#define XSTR (Tlen * XW) // x packed row stride per batch   (12800)

// ---------------------------------------------------------------------------
// Persistent device scratch (static __device__ arrays — no cudaMalloc).
// h state stored PRE-SPLIT as packed bf16x2 (hi/lo), ping-pong buffered.
// ---------------------------------------------------------------------------
__device__ uint32_t g_h1h[2][Bsz * HW];
__device__ uint32_t g_h1l[2][Bsz * HW];
__device__ uint32_t g_h2h[2][Bsz * HW];
__device__ uint32_t g_h2l[2][Bsz * HW];
__device__ float    g_c1[Bsz * Hdim];
__device__ float    g_c2[Bsz * Hdim];
__device__ float    g_sum[Bsz * Hdim];

// Pre-split x: packed bf16x2 words, layout [b][t][f/2].
__device__ uint32_t g_xh[Bsz * Tlen * XW];
__device__ uint32_t g_xl[Bsz * Tlen * XW];

// Weights: gate-interleaved cols (h*4+g), bf16 hi/lo split, FRAGMENT-ordered:
// per (strip s, chunk c): 1024 words = [hl][ks2][r][lane][nt]
//   word = hl*512 + ks2*256 + r*128 + lane*4 + nt
__device__ uint32_t g_W1f[32 * NC1 * 1024];
__device__ uint32_t g_W2f[32 * NC2 * 1024];
__device__ float    g_b1r[G4H];
__device__ float    g_b2r[G4H];

// ---------------------------------------------------------------------------
// helpers
// ---------------------------------------------------------------------------
__device__ __forceinline__ float bfr(float a) {          // bf16-rounded value
    return __bfloat162float(__float2bfloat16(a));
}
// pack two fp32 as bf16x2: low half = e0, high half = e1
__device__ __forceinline__ uint32_t packbf(float e0, float e1) {
    uint32_t d;
    asm("cvt.rn.bf16x2.f32 %0, %1, %2;" : "=r"(d) : "f"(e1), "f"(e0));
    return d;
}

__device__ __forceinline__ void mma_bf16(float* c, const uint32_t* a,
                                         const uint32_t* b) {
    asm volatile(
        "mma.sync.aligned.m16n8k16.row.col.f32.bf16.bf16.f32 "
        "{%0,%1,%2,%3}, {%4,%5,%6,%7}, {%8,%9}, {%0,%1,%2,%3};"
        : "+f"(c[0]), "+f"(c[1]), "+f"(c[2]), "+f"(c[3])
        : "r"(a[0]), "r"(a[1]), "r"(a[2]), "r"(a[3]), "r"(b[0]), "r"(b[1]));
}

#define CPASYNC16(dst, src) \
    asm volatile("cp.async.ca.shared.global [%0], [%1], 16;" :: "r"(dst), "l"(src))
#define CP_COMMIT() asm volatile("cp.async.commit_group;")
#define CP_WAIT1()  asm volatile("cp.async.wait_group 1;")

__device__ __forceinline__ float fast_sig(float v)  { return 1.0f / (1.0f + __expf(-v)); }
__device__ __forceinline__ float fast_tanh(float v) { return 1.0f - 2.0f / (__expf(2.0f * v) + 1.0f); }

// ---------------------------------------------------------------------------
// Prolog: split x into packed bf16x2 hi/lo
// ---------------------------------------------------------------------------
__global__ void split_x_kernel(const float* __restrict__ x)
{
    const int n4 = (Bsz * Tlen * Fdim) / 4;      // float4 count
    for (int i = blockIdx.x * blockDim.x + threadIdx.x; i < n4;
         i += gridDim.x * blockDim.x) {
        float4 v = ((const float4*)x)[i];
        uint2 wh, wl;
        wh.x = packbf(v.x, v.y);
        wh.y = packbf(v.z, v.w);
        wl.x = packbf(v.x - bfr(v.x), v.y - bfr(v.y));
        wl.y = packbf(v.z - bfr(v.z), v.w - bfr(v.w));
        ((uint2*)g_xh)[i] = wh;
        ((uint2*)g_xl)[i] = wl;
    }
}

// ---------------------------------------------------------------------------
// Prolog: weight reorder into fragment order + bf16 hi/lo split.
// Source W is [K, 4H] with column g*H+h; gate-interleaved col = h*4+g.
// ---------------------------------------------------------------------------
__global__ void reorder_frag(const float* __restrict__ W,
                             const float* __restrict__ bias,
                             int NC, int which)
{
    uint32_t* Wf = which ? g_W2f : g_W1f;
    float*    bd = which ? g_b2r : g_b1r;
    const int n = 32 * NC * 1024;
    for (int idx = blockIdx.x * blockDim.x + threadIdx.x; idx < n;
         idx += gridDim.x * blockDim.x) {
        int nt   = idx & 3;
        int lane = (idx >> 2) & 31;
        int r    = (idx >> 7) & 1;
        int ks2  = (idx >> 8) & 1;
        int hl   = (idx >> 9) & 1;
        int sc   = idx >> 10;
        int c    = sc % NC;
        int s    = sc / NC;

        int k0  = c * 32 + ks2 * 16 + r * 8 + 2 * (lane & 3);
        int col = s * 32 + nt * 8 + (lane >> 2);
        int h = col >> 2, g = col & 3;
        float w0 = W[k0 * G4H + g * Hdim + h];
        float w1 = W[(k0 + 1) * G4H + g * Hdim + h];
        Wf[idx] = (hl == 0)
            ? packbf(w0, w1)
            : packbf(w0 - bfr(w0), w1 - bfr(w1));

        if (idx < G4H) {
            int hh = idx >> 2, gg = idx & 3;
            bd[idx] = bias[gg * Hdim + hh];
        }
    }
}

__global__ void zero_kernel()
{
    int idx = blockIdx.x * blockDim.x + threadIdx.x;
    if (idx < Bsz * Hdim) {
        g_c1[idx] = 0.0f; g_c2[idx] = 0.0f; g_sum[idx] = 0.0f;
    }
    if (idx < Bsz * HW) {
        g_h1h[0][idx] = 0u; g_h1l[0][idx] = 0u;
        g_h2h[0][idx] = 0u; g_h2l[0][idx] = 0u;
    }
}

// ---------------------------------------------------------------------------
// bf16 mma.sync LSTM step kernel.
// CTA: 128 batch rows x 128 gate cols. 512 threads = 16 warps (4 row x 4 col),
// warp tile 32x32 (2 m16 x 4 n8). K chunked by 32 (2 k16 steps), cp.async
// double buffered. A operands pre-split/packed (zero cvt in loop); B operands
// fragment-ordered (LDS.128). 3-term bf16 split, fp32 accumulate.
//
// Smem (words): stage s at s*9216:
//   [0,2560)    A hi : 128 rows x 20-word stride (16 data + 4 pad)
//   [2560,5120) A lo
//   [5120,9216) B    : 4 strips x 1024 words  ([hl][ks2][r][lane][nt])
// ---------------------------------------------------------------------------
#define ASTR   20
#define A_LO_W 2560
#define B_W    5120
#define STGW   9216
#define STGB   (STGW * 4)          // 36864 B
#define SMEM_TOTAL (2 * STGB)      // 73728 B
#define ZSTR   132

template <int LAYER>
__global__ void __launch_bounds__(512, 1)
lstm_step_bf16(const int* __restrict__ lengths, int t)
{
    constexpr int NC  = (LAYER == 1) ? NC1 : NC2;
    constexpr int W0C = (LAYER == 1) ? 4 : 8;     // chunks from segment 0

    extern __shared__ uint32_t smw[];
    uint32_t smb;
    asm("{ .reg .u64 t0; cvta.to.shared.u64 t0, %1; cvt.u32.u64 %0, t0; }"
        : "=r"(smb) : "l"(smw));

    const uint32_t* __restrict__ Wf = (LAYER == 1) ? g_W1f : g_W2f;
    const float*    __restrict__ bd = (LAYER == 1) ? g_b1r : g_b2r;

    const int p = t & 1;
    // segment-0 source (packed hi/lo) + word stride + k-word base
    const uint32_t* __restrict__ s0h;
    const uint32_t* __restrict__ s0l;
    size_t s0s; size_t s0k;
    if (LAYER == 1) { s0h = g_xh; s0l = g_xl; s0s = XSTR; s0k = (size_t)t * XW; }
    else            { s0h = g_h1h[p ^ 1]; s0l = g_h1l[p ^ 1]; s0s = HW; s0k = 0; }
    const uint32_t* __restrict__ hph = (LAYER == 1) ? g_h1h[p] : g_h2h[p];
    const uint32_t* __restrict__ hpl = (LAYER == 1) ? g_h1l[p] : g_h2l[p];
    uint32_t* __restrict__ hnh = (LAYER == 1) ? g_h1h[p ^ 1] : g_h2h[p ^ 1];
    uint32_t* __restrict__ hnl = (LAYER == 1) ? g_h1l[p ^ 1] : g_h2l[p ^ 1];
    float*    __restrict__ cst = (LAYER == 1) ? g_c1 : g_c2;

    const int tid  = threadIdx.x;
    const int lane = tid & 31;
    const int gq   = lane >> 2;
    const int rq   = lane & 3;
    const int wid  = tid >> 5;
    const int wr   = wid & 3;      // warp row (32 rows)
    const int wcol = wid >> 2;     // warp col strip (32 cols)
    const int col0 = blockIdx.x * 128;
    const int row0 = blockIdx.y * 128;
    const int s0strip = blockIdx.x * 4;

    // ---- producer ----
    const int prow = tid >> 2;     // 0..127
    const int pq   = tid & 3;      // 16B quad within row chunk

    auto fill = [&](int c) {
        const uint32_t sb = smb + (uint32_t)(c & 1) * STGB;
        // A: one 16B op for hi + one for lo per thread
        size_t off;
        const uint32_t *ph, *pl;
        if (c < W0C) {
            ph = s0h; pl = s0l;
            off = (size_t)(row0 + prow) * s0s + s0k + c * 16 + pq * 4;
        } else {
            ph = hph; pl = hpl;
            off = (size_t)(row0 + prow) * HW + (c - W0C) * 16 + pq * 4;
        }
        const uint32_t adst = sb + (uint32_t)(prow * ASTR + pq * 4) * 4u;
        CPASYNC16(adst, ph + off);
        CPASYNC16(adst + A_LO_W * 4u, pl + off);
        // B: 2 x 16B per thread
#pragma unroll
        for (int o = 0; o < 2; o++) {
            const int oo = tid + o * 512;         // 0..1023
            const int j = oo >> 8;
            const int w = (oo & 255) * 4;
            const uint32_t* src = Wf + ((size_t)(s0strip + j) * NC + c) * 1024 + w;
            CPASYNC16(sb + (uint32_t)(B_W + j * 1024 + w) * 4u, src);
        }
    };

    float acc[2][4][4];
#pragma unroll
    for (int mt = 0; mt < 2; mt++)
#pragma unroll
        for (int nt = 0; nt < 4; nt++)
#pragma unroll
            for (int q = 0; q < 4; q++) acc[mt][nt][q] = 0.0f;

    fill(0);
    CP_COMMIT();

#pragma unroll 1
    for (int c = 0; c < NC; c++) {
        if (c + 1 < NC) fill(c + 1);
        CP_COMMIT();
        CP_WAIT1();
        __syncthreads();

        const uint32_t* ash = smw + (c & 1) * STGW;
        const uint32_t* asl = ash + A_LO_W;
        const uint32_t* bb  = ash + B_W + wcol * 1024;

#pragma unroll
        for (int ks2 = 0; ks2 < 2; ks2++) {
            uint32_t bh0[4], bh1[4], bl0[4], bl1[4];
            *(uint4*)bh0 = *(const uint4*)(bb + ks2 * 256 + lane * 4);
            *(uint4*)bh1 = *(const uint4*)(bb + ks2 * 256 + 128 + lane * 4);
            *(uint4*)bl0 = *(const uint4*)(bb + 512 + ks2 * 256 + lane * 4);
            *(uint4*)bl1 = *(const uint4*)(bb + 512 + ks2 * 256 + 128 + lane * 4);

            const int kw = ks2 * 8 + rq;
#pragma unroll
            for (int mt = 0; mt < 2; mt++) {
                const int r0 = wr * 32 + mt * 16 + gq;
                uint32_t ah[4], al[4];
                ah[0] = ash[r0 * ASTR + kw];
                ah[1] = ash[(r0 + 8) * ASTR + kw];
                ah[2] = ash[r0 * ASTR + kw + 4];
                ah[3] = ash[(r0 + 8) * ASTR + kw + 4];
                al[0] = asl[r0 * ASTR + kw];
                al[1] = asl[(r0 + 8) * ASTR + kw];
                al[2] = asl[r0 * ASTR + kw + 4];
                al[3] = asl[(r0 + 8) * ASTR + kw + 4];
#pragma unroll
                for (int nt = 0; nt < 4; nt++) {
                    uint32_t bhp[2] = { bh0[nt], bh1[nt] };
                    uint32_t blp[2] = { bl0[nt], bl1[nt] };
                    mma_bf16(acc[mt][nt], ah, bhp);
                    mma_bf16(acc[mt][nt], ah, blp);
                    mma_bf16(acc[mt][nt], al, bhp);
                }
            }
        }
        __syncthreads();
    }

    // ---- stage Z in smem ----
    float* Zs = (float*)smw;
#pragma unroll
    for (int mt = 0; mt < 2; mt++)
#pragma unroll
        for (int nt = 0; nt < 4; nt++) {
            const int row = wr * 32 + mt * 16 + gq;
            const int col = wcol * 32 + nt * 8 + 2 * rq;
            Zs[row * ZSTR + col]           = acc[mt][nt][0];
            Zs[row * ZSTR + col + 1]       = acc[mt][nt][1];
            Zs[(row + 8) * ZSTR + col]     = acc[mt][nt][2];
            Zs[(row + 8) * ZSTR + col + 1] = acc[mt][nt][3];
        }
    __syncthreads();

    // ---- fused LSTM cell: thread = 1 row x 8 units (4 packed words) ----
    {
        const int row  = tid >> 2;
        const int ub   = (tid & 3) * 8;         // local unit base (even)
        const int rowg = row0 + row;
        const bool valid = (t < lengths[rowg]);
        const int gu0 = (col0 >> 2) + ub;       // global unit base (even)
        const size_t hw0 = (size_t)rowg * HW + (gu0 >> 1);

        if (valid) {
#pragma unroll
            for (int u2 = 0; u2 < 4; u2++) {
                float nhv[2];
#pragma unroll
                for (int e = 0; e < 2; e++) {
                    const int lu  = ub + 2 * u2 + e;       // local unit
                    const int n4  = lu * 4;
                    const int idx = rowg * Hdim + (col0 >> 2) + lu;
                    float4 z  = *(const float4*)&Zs[row * ZSTR + n4];
                    float4 bv = *(const float4*)&bd[col0 + n4];
                    const float zi = z.x + bv.x;
                    const float zj = z.y + bv.y;
                    const float zf = z.z + bv.z;
                    const float zo = z.w + bv.w;
                    const float nc = cst[idx] * fast_sig(zf + 1.0f)
                                   + fast_sig(zi) * fast_tanh(zj);
                    const float nh = fast_tanh(nc) * fast_sig(zo);
                    cst[idx] = nc;
                    if (LAYER == 2) g_sum[idx] += nh;
                    nhv[e] = nh;
                }
                hnh[hw0 + u2] = packbf(nhv[0], nhv[1]);
                hnl[hw0 + u2] = packbf(nhv[0] - bfr(nhv[0]),
                                       nhv[1] - bfr(nhv[1]));
            }
        } else {
#pragma unroll
            for (int u2 = 0; u2 < 4; u2++) {
                hnh[hw0 + u2] = hph[hw0 + u2];
                hnl[hw0 + u2] = hpl[hw0 + u2];
            }
        }
    }
}

// ---------------------------------------------------------------------------
// logits[b,o] = dot(sum[b,:], Wout[:,o]) / lengths[b] + bout[o]
// ---------------------------------------------------------------------------
__global__ void final_kernel(const int* __restrict__ lengths,
                             const float* __restrict__ Wout,
                             const float* __restrict__ bout,
                             float* __restrict__ out)
{
    const int idx = blockIdx.x * blockDim.x + threadIdx.x;
    if (idx >= Bsz * Odim) return;
    const int b = idx / Odim;
    const int o = idx % Odim;
    const float* s = g_sum + b * Hdim;
    float acc = 0.0f;
#pragma unroll 8
    for (int h = 0; h < Hdim; h++) acc += s[h] * Wout[h * Odim + o];
    out[idx] = acc / (float)lengths[b] + bout[o];
}

// ---------------------------------------------------------------------------
// Inputs (metadata order): x, lengths, W1, b1, W2, b2, Wout, bout
// ---------------------------------------------------------------------------
extern "C" void kernel_launch(void* const* d_in, const int* in_sizes, int n_in,
                              void* d_out, int out_size)
{
    const float* x       = (const float*)d_in[0];
    const int*   lengths = (const int*)d_in[1];
    const float* W1      = (const float*)d_in[2];
    const float* b1      = (const float*)d_in[3];
    const float* W2      = (const float*)d_in[4];
    const float* b2      = (const float*)d_in[5];
    const float* Wout    = (const float*)d_in[6];
    const float* bout    = (const float*)d_in[7];
    float* out = (float*)d_out;

    cudaFuncSetAttribute(lstm_step_bf16<1>,
                         cudaFuncAttributeMaxDynamicSharedMemorySize, SMEM_TOTAL);
    cudaFuncSetAttribute(lstm_step_bf16<2>,
                         cudaFuncAttributeMaxDynamicSharedMemorySize, SMEM_TOTAL);

    split_x_kernel<<<4096, 256>>>(x);
    reorder_frag<<<1536, 256>>>(W1, b1, NC1, 0);
    reorder_frag<<<2048, 256>>>(W2, b2, NC2, 1);
    zero_kernel<<<(Bsz * Hdim) / 256, 256>>>();

    dim3 grid(G4H / 128, Bsz / 128);   // (8, 16) = 128 CTAs
    for (int t = 0; t < Tlen; t++) {
        lstm_step_bf16<1><<<grid, 512, SMEM_TOTAL>>>(lengths, t);
        lstm_step_bf16<2><<<grid, 512, SMEM_TOTAL>>>(lengths, t);
    }

    final_kernel<<<(Bsz * Odim + 255) / 256, 256>>>(lengths, Wout, bout, out);
}

// round 8
// speedup vs baseline: 2.3699x; 1.0946x over previous
#include <cuda_runtime.h>
#include <cuda_bf16.h>
#include <math.h>
#include <stdint.h>

// Problem constants
#define Bsz  2048
#define Tlen 200
#define Fdim 128
#define Hdim 256
#define Odim 6
#define G4H  1024
#define NC1  12          // 384/32
#define NC2  16          // 512/32
#define HW   (Hdim / 2)  // packed bf16x2 words per h row  (128)
#define XW   (Fdim / 2)  // packed words per x row          (64)
#define XSTR (Tlen * XW) // x packed row stride per batch

// ---------------------------------------------------------------------------
// Persistent device scratch. h state PRE-SPLIT packed bf16x2 (hi/lo),
// ping-pong buffered. c/sum live in REGISTERS inside the persistent kernel.
// ---------------------------------------------------------------------------
__device__ uint32_t g_h1h[2][Bsz * HW];
__device__ uint32_t g_h1l[2][Bsz * HW];
__device__ uint32_t g_h2h[2][Bsz * HW];
__device__ uint32_t g_h2l[2][Bsz * HW];
__device__ float    g_sum[Bsz * Hdim];
__device__ unsigned g_bar[16];             // one barrier counter per row block

// Pre-split x: packed bf16x2 words, layout [b][t][f/2].
__device__ uint32_t g_xh[Bsz * Tlen * XW];
__device__ uint32_t g_xl[Bsz * Tlen * XW];

// Weights: gate-interleaved cols (h*4+g), bf16 hi/lo split, FRAGMENT-ordered:
// per (strip s, chunk c): 1024 words = [hl][ks2][r][lane][nt]
__device__ uint32_t g_W1f[32 * NC1 * 1024];
__device__ uint32_t g_W2f[32 * NC2 * 1024];
__device__ float    g_b1r[G4H];
__device__ float    g_b2r[G4H];

// ---------------------------------------------------------------------------
// helpers
// ---------------------------------------------------------------------------
__device__ __forceinline__ float bfr(float a) {
    return __bfloat162float(__float2bfloat16(a));
}
__device__ __forceinline__ uint32_t packbf(float e0, float e1) {
    uint32_t d;
    asm("cvt.rn.bf16x2.f32 %0, %1, %2;" : "=r"(d) : "f"(e1), "f"(e0));
    return d;
}
__device__ __forceinline__ void mma_bf16(float* c, const uint32_t* a,
                                         const uint32_t* b) {
    asm volatile(
        "mma.sync.aligned.m16n8k16.row.col.f32.bf16.bf16.f32 "
        "{%0,%1,%2,%3}, {%4,%5,%6,%7}, {%8,%9}, {%0,%1,%2,%3};"
        : "+f"(c[0]), "+f"(c[1]), "+f"(c[2]), "+f"(c[3])
        : "r"(a[0]), "r"(a[1]), "r"(a[2]), "r"(a[3]), "r"(b[0]), "r"(b[1]));
}

#define CPASYNC16(dst, src) \
    asm volatile("cp.async.ca.shared.global [%0], [%1], 16;" :: "r"(dst), "l"(src))
#define CPASYNC16CG(dst, src) \
    asm volatile("cp.async.cg.shared.global [%0], [%1], 16;" :: "r"(dst), "l"(src))
#define CP_COMMIT() asm volatile("cp.async.commit_group;")
#define CP_WAIT0()  asm volatile("cp.async.wait_group 0;")

__device__ __forceinline__ float fast_sig(float v)  { return 1.0f / (1.0f + __expf(-v)); }
__device__ __forceinline__ float fast_tanh(float v) { return 1.0f - 2.0f / (__expf(2.0f * v) + 1.0f); }

// ---------------------------------------------------------------------------
// Prolog: split x into packed bf16x2 hi/lo
// ---------------------------------------------------------------------------
__global__ void split_x_kernel(const float* __restrict__ x)
{
    const int n4 = (Bsz * Tlen * Fdim) / 4;
    for (int i = blockIdx.x * blockDim.x + threadIdx.x; i < n4;
         i += gridDim.x * blockDim.x) {
        float4 v = ((const float4*)x)[i];
        uint2 wh, wl;
        wh.x = packbf(v.x, v.y);
        wh.y = packbf(v.z, v.w);
        wl.x = packbf(v.x - bfr(v.x), v.y - bfr(v.y));
        wl.y = packbf(v.z - bfr(v.z), v.w - bfr(v.w));
        ((uint2*)g_xh)[i] = wh;
        ((uint2*)g_xl)[i] = wl;
    }
}

// ---------------------------------------------------------------------------
// Prolog: weight reorder into fragment order + bf16 hi/lo split.
// ---------------------------------------------------------------------------
__global__ void reorder_frag(const float* __restrict__ W,
                             const float* __restrict__ bias,
                             int NC, int which)
{
    uint32_t* Wf = which ? g_W2f : g_W1f;
    float*    bd = which ? g_b2r : g_b1r;
    const int n = 32 * NC * 1024;
    for (int idx = blockIdx.x * blockDim.x + threadIdx.x; idx < n;
         idx += gridDim.x * blockDim.x) {
        int nt   = idx & 3;
        int lane = (idx >> 2) & 31;
        int r    = (idx >> 7) & 1;
        int ks2  = (idx >> 8) & 1;
        int hl   = (idx >> 9) & 1;
        int sc   = idx >> 10;
        int c    = sc % NC;
        int s    = sc / NC;

        int k0  = c * 32 + ks2 * 16 + r * 8 + 2 * (lane & 3);
        int col = s * 32 + nt * 8 + (lane >> 2);
        int h = col >> 2, g = col & 3;
        float w0 = W[k0 * G4H + g * Hdim + h];
        float w1 = W[(k0 + 1) * G4H + g * Hdim + h];
        Wf[idx] = (hl == 0)
            ? packbf(w0, w1)
            : packbf(w0 - bfr(w0), w1 - bfr(w1));

        if (idx < G4H) {
            int hh = idx >> 2, gg = idx & 3;
            bd[idx] = bias[gg * Hdim + hh];
        }
    }
}

__global__ void zero_kernel()
{
    int idx = blockIdx.x * blockDim.x + threadIdx.x;
    if (idx < 16) g_bar[idx] = 0u;
    if (idx < Bsz * HW) {
        g_h1h[0][idx] = 0u; g_h1l[0][idx] = 0u;
        g_h2h[0][idx] = 0u; g_h2l[0][idx] = 0u;
    }
}

// ---------------------------------------------------------------------------
// Persistent LSTM kernel: 128 CTAs (16 row blocks x 8 col strips), all 200
// timesteps x 2 layers inside. Cross-CTA deps are row-block local, so one
// 8-CTA release/acquire barrier per timestep (after layer 1); the chain
// L2(t-1) -> L1(t) -> barrier(t) -> L2(t) transitively covers all h2
// hazards. c1/c2/sum in registers for the whole sequence. GEMM: bf16
// m16n8k16 3-term split, cp.async double buffer, one __syncthreads/K-chunk.
// 128 CTAs <= 148 SMs and 1 CTA/SM => full co-residency (spin barrier safe).
// ---------------------------------------------------------------------------
#define ASTR   20
#define A_LO_W 2560
#define B_W    5120
#define STGW   9216
#define STGB   (STGW * 4)          // 36864 B
#define SMEM_TOTAL (2 * STGB)      // 73728 B
#define ZSTR   132

struct TagL1 { static constexpr int L = 1; };
struct TagL2 { static constexpr int L = 2; };

__global__ void __launch_bounds__(512, 1)
lstm_persist(const int* __restrict__ lengths)
{
    extern __shared__ uint32_t smw[];
    uint32_t smb;
    asm("{ .reg .u64 t0; cvta.to.shared.u64 t0, %1; cvt.u32.u64 %0, t0; }"
        : "=r"(smb) : "l"(smw));

    const int tid  = threadIdx.x;
    const int lane = tid & 31;
    const int gq   = lane >> 2;
    const int rq   = lane & 3;
    const int wid  = tid >> 5;
    const int wr   = wid & 3;        // warp row (32 rows)
    const int wcol = wid >> 2;       // warp col strip (32 cols)
    const int rb   = blockIdx.x >> 3;
    const int cs   = blockIdx.x & 7;
    const int row0 = rb * 128;
    const int col0 = cs * 128;
    const int s0strip = cs * 4;
    const int prow = tid >> 2;       // producer row
    const int pq   = tid & 3;
    const int erow = tid >> 2;       // epilogue row
    const int eub  = (tid & 3) * 8;  // epilogue unit base
    const int mylen = lengths[row0 + erow];
    unsigned* barp = &g_bar[rb];

    float c1r[8], c2r[8], sumr[8];
#pragma unroll
    for (int u = 0; u < 8; u++) { c1r[u] = 0.f; c2r[u] = 0.f; sumr[u] = 0.f; }

    auto phase = [&](auto tag, int t, float* creg) {
        constexpr int LAYER = decltype(tag)::L;
        constexpr int NC  = (LAYER == 1) ? NC1 : NC2;
        constexpr int W0C = (LAYER == 1) ? 4 : 8;   // chunks from segment 0
        const uint32_t* __restrict__ Wf = (LAYER == 1) ? g_W1f : g_W2f;
        const float*    __restrict__ bd = (LAYER == 1) ? g_b1r : g_b2r;

        const int p = t & 1;
        const uint32_t* s0h; const uint32_t* s0l; size_t s0s, s0k;
        if (LAYER == 1) { s0h = g_xh; s0l = g_xl; s0s = XSTR; s0k = (size_t)t * XW; }
        else            { s0h = g_h1h[p ^ 1]; s0l = g_h1l[p ^ 1]; s0s = HW; s0k = 0; }
        const uint32_t* hph = (LAYER == 1) ? g_h1h[p] : g_h2h[p];
        const uint32_t* hpl = (LAYER == 1) ? g_h1l[p] : g_h2l[p];
        uint32_t* hnh = (LAYER == 1) ? g_h1h[p ^ 1] : g_h2h[p ^ 1];
        uint32_t* hnl = (LAYER == 1) ? g_h1l[p ^ 1] : g_h2l[p ^ 1];

        auto fill = [&](int c) {
            const uint32_t sb = smb + (uint32_t)(c & 1) * STGB;
            size_t off; const uint32_t *ph, *pl;
            if (c < W0C) {
                ph = s0h; pl = s0l;
                off = (size_t)(row0 + prow) * s0s + s0k + c * 16 + pq * 4;
            } else {
                ph = hph; pl = hpl;
                off = (size_t)(row0 + prow) * HW + (c - W0C) * 16 + pq * 4;
            }
            const uint32_t adst = sb + (uint32_t)(prow * ASTR + pq * 4) * 4u;
            CPASYNC16CG(adst, ph + off);                 // .cg: no stale L1
            CPASYNC16CG(adst + A_LO_W * 4u, pl + off);
#pragma unroll
            for (int o = 0; o < 2; o++) {
                const int oo = tid + o * 512;
                const int j = oo >> 8;
                const int w = (oo & 255) * 4;
                const uint32_t* src = Wf + ((size_t)(s0strip + j) * NC + c) * 1024 + w;
                CPASYNC16(sb + (uint32_t)(B_W + j * 1024 + w) * 4u, src);
            }
        };

        float acc[2][4][4];
#pragma unroll
        for (int mt = 0; mt < 2; mt++)
#pragma unroll
            for (int nt = 0; nt < 4; nt++)
#pragma unroll
                for (int q = 0; q < 4; q++) acc[mt][nt][q] = 0.0f;

        fill(0);
        CP_COMMIT();

#pragma unroll 1
        for (int c = 0; c < NC; c++) {
            CP_WAIT0();            // chunk c landed
            __syncthreads();       // data published + prior compute done
            if (c + 1 < NC) { fill(c + 1); CP_COMMIT(); }

            const uint32_t* ash = smw + (c & 1) * STGW;
            const uint32_t* asl = ash + A_LO_W;
            const uint32_t* bb  = ash + B_W + wcol * 1024;

#pragma unroll
            for (int ks2 = 0; ks2 < 2; ks2++) {
                uint32_t bh0[4], bh1[4], bl0[4], bl1[4];
                *(uint4*)bh0 = *(const uint4*)(bb + ks2 * 256 + lane * 4);
                *(uint4*)bh1 = *(const uint4*)(bb + ks2 * 256 + 128 + lane * 4);
                *(uint4*)bl0 = *(const uint4*)(bb + 512 + ks2 * 256 + lane * 4);
                *(uint4*)bl1 = *(const uint4*)(bb + 512 + ks2 * 256 + 128 + lane * 4);

                const int kw = ks2 * 8 + rq;
#pragma unroll
                for (int mt = 0; mt < 2; mt++) {
                    const int r0 = wr * 32 + mt * 16 + gq;
                    uint32_t ah[4], al[4];
                    ah[0] = ash[r0 * ASTR + kw];
                    ah[1] = ash[(r0 + 8) * ASTR + kw];
                    ah[2] = ash[r0 * ASTR + kw + 4];
                    ah[3] = ash[(r0 + 8) * ASTR + kw + 4];
                    al[0] = asl[r0 * ASTR + kw];
                    al[1] = asl[(r0 + 8) * ASTR + kw];
                    al[2] = asl[r0 * ASTR + kw + 4];
                    al[3] = asl[(r0 + 8) * ASTR + kw + 4];
#pragma unroll
                    for (int nt = 0; nt < 4; nt++) {
                        uint32_t bhp[2] = { bh0[nt], bh1[nt] };
                        uint32_t blp[2] = { bl0[nt], bl1[nt] };
                        mma_bf16(acc[mt][nt], ah, bhp);
                        mma_bf16(acc[mt][nt], ah, blp);
                        mma_bf16(acc[mt][nt], al, bhp);
                    }
                }
            }
        }
        __syncthreads();   // all compute done before Z overwrites stages

        // ---- stage Z in smem ----
        float* Zs = (float*)smw;
#pragma unroll
        for (int mt = 0; mt < 2; mt++)
#pragma unroll
            for (int nt = 0; nt < 4; nt++) {
                const int row = wr * 32 + mt * 16 + gq;
                const int col = wcol * 32 + nt * 8 + 2 * rq;
                Zs[row * ZSTR + col]           = acc[mt][nt][0];
                Zs[row * ZSTR + col + 1]       = acc[mt][nt][1];
                Zs[(row + 8) * ZSTR + col]     = acc[mt][nt][2];
                Zs[(row + 8) * ZSTR + col + 1] = acc[mt][nt][3];
            }
        __syncthreads();

        // ---- fused LSTM cell: thread = 1 row x 8 units, c/sum in regs ----
        {
            const bool valid = (t < mylen);
            const int rowg = row0 + erow;
            const int gu0  = (col0 >> 2) + eub;
            const size_t hw0 = (size_t)rowg * HW + (gu0 >> 1);
            if (valid) {
#pragma unroll
                for (int u2 = 0; u2 < 4; u2++) {
                    float nhv[2];
#pragma unroll
                    for (int e = 0; e < 2; e++) {
                        const int uu = 2 * u2 + e;
                        const int n4 = (eub + uu) * 4;
                        float4 z  = *(const float4*)&Zs[erow * ZSTR + n4];
                        float4 bv = *(const float4*)&bd[col0 + n4];
                        const float zi = z.x + bv.x;
                        const float zj = z.y + bv.y;
                        const float zf = z.z + bv.z;
                        const float zo = z.w + bv.w;
                        const float nc = creg[uu] * fast_sig(zf + 1.0f)
                                       + fast_sig(zi) * fast_tanh(zj);
                        const float nh = fast_tanh(nc) * fast_sig(zo);
                        creg[uu] = nc;
                        if (LAYER == 2) sumr[uu] += nh;
                        nhv[e] = nh;
                    }
                    hnh[hw0 + u2] = packbf(nhv[0], nhv[1]);
                    hnl[hw0 + u2] = packbf(nhv[0] - bfr(nhv[0]),
                                           nhv[1] - bfr(nhv[1]));
                }
            } else {
#pragma unroll
                for (int u2 = 0; u2 < 4; u2++) {
                    hnh[hw0 + u2] = hph[hw0 + u2];
                    hnl[hw0 + u2] = hpl[hw0 + u2];
                }
            }
        }
        __syncthreads();   // Z reads done before next phase's fill
    };

#pragma unroll 1
    for (int t = 0; t < Tlen; t++) {
        phase(TagL1{}, t, c1r);
        // 8-CTA row-block barrier (release/acquire, cumulative)
        if (tid == 0) {
            asm volatile("red.release.gpu.add.u32 [%0], 1;" :: "l"(barp) : "memory");
            const unsigned tgt = 8u * (unsigned)(t + 1);
            unsigned v;
            while (true) {
                asm volatile("ld.acquire.gpu.b32 %0, [%1];"
                             : "=r"(v) : "l"(barp) : "memory");
                if (v >= tgt) break;
                asm volatile("nanosleep.u32 64;");
            }
        }
        __syncthreads();
        phase(TagL2{}, t, c2r);
    }

    // write accumulated sums once
    {
        const int rowg = row0 + erow;
        const int gu0  = (col0 >> 2) + eub;
#pragma unroll
        for (int u = 0; u < 8; u++)
            g_sum[rowg * Hdim + gu0 + u] = sumr[u];
    }
}

// ---------------------------------------------------------------------------
// logits[b,o] = dot(sum[b,:], Wout[:,o]) / lengths[b] + bout[o]
// ---------------------------------------------------------------------------
__global__ void final_kernel(const int* __restrict__ lengths,
                             const float* __restrict__ Wout,
                             const float* __restrict__ bout,
                             float* __restrict__ out)
{
    const int idx = blockIdx.x * blockDim.x + threadIdx.x;
    if (idx >= Bsz * Odim) return;
    const int b = idx / Odim;
    const int o = idx % Odim;
    const float* s = g_sum + b * Hdim;
    float acc = 0.0f;
#pragma unroll 8
    for (int h = 0; h < Hdim; h++) acc += s[h] * Wout[h * Odim + o];
    out[idx] = acc / (float)lengths[b] + bout[o];
}

// ---------------------------------------------------------------------------
// Inputs (metadata order): x, lengths, W1, b1, W2, b2, Wout, bout
// ---------------------------------------------------------------------------
extern "C" void kernel_launch(void* const* d_in, const int* in_sizes, int n_in,
                              void* d_out, int out_size)
{
    const float* x       = (const float*)d_in[0];
    const int*   lengths = (const int*)d_in[1];
    const float* W1      = (const float*)d_in[2];
    const float* b1      = (const float*)d_in[3];
    const float* W2      = (const float*)d_in[4];
    const float* b2      = (const float*)d_in[5];
    const float* Wout    = (const float*)d_in[6];
    const float* bout    = (const float*)d_in[7];
    float* out = (float*)d_out;

    cudaFuncSetAttribute(lstm_persist,
                         cudaFuncAttributeMaxDynamicSharedMemorySize, SMEM_TOTAL);

    split_x_kernel<<<4096, 256>>>(x);
    reorder_frag<<<1536, 256>>>(W1, b1, NC1, 0);
    reorder_frag<<<2048, 256>>>(W2, b2, NC2, 1);
    zero_kernel<<<1024, 256>>>();

    lstm_persist<<<128, 512, SMEM_TOTAL>>>(lengths);

    final_kernel<<<(Bsz * Odim + 255) / 256, 256>>>(lengths, Wout, bout, out);
}

// round 10
// speedup vs baseline: 2.6176x; 1.1045x over previous
#include <cuda_runtime.h>
#include <cuda_bf16.h>
#include <math.h>
#include <stdint.h>

// Problem constants
#define Bsz  2048
#define Tlen 200
#define Fdim 128
#define Hdim 256
#define Odim 6
#define G4H  1024
#define NC1  12          // 384/32
#define NC2  16          // 512/32
#define HW   (Hdim / 2)  // packed bf16x2 words per h row  (128)
#define XW   (Fdim / 2)  // packed words per x row          (64)
#define XSTR (Tlen * XW) // x packed row stride per batch

// ---------------------------------------------------------------------------
// Persistent device scratch. ALL batch-indexed arrays use SORTED row order
// (rows sorted by length descending; perm maps sorted -> original).
// ---------------------------------------------------------------------------
__device__ uint32_t g_h1h[2][Bsz * HW];
__device__ uint32_t g_h1l[2][Bsz * HW];
__device__ uint32_t g_h2h[2][Bsz * HW];
__device__ uint32_t g_h2l[2][Bsz * HW];
__device__ float    g_c1[Bsz * Hdim];
__device__ float    g_c2[Bsz * Hdim];
__device__ float    g_sum[Bsz * Hdim];
__device__ int      g_perm[Bsz];      // sorted row -> original row
__device__ int      g_lenS[Bsz];      // sorted lengths (descending)
__device__ int      g_nbArr[Tlen];    // active row-block count per step (16/8/4)
__device__ unsigned g_bar;            // global step barrier counter

// Pre-split x (SORTED rows): packed bf16x2 words, layout [srow][t][f/2].
__device__ uint32_t g_xh[Bsz * Tlen * XW];
__device__ uint32_t g_xl[Bsz * Tlen * XW];

// Weights: gate-interleaved cols (h*4+g), bf16 hi/lo split, FRAGMENT-ordered:
// per (32-col strip s, chunk c): 1024 words = [hl][ks2][r][lane][nt]
__device__ uint32_t g_W1f[32 * NC1 * 1024];
__device__ uint32_t g_W2f[32 * NC2 * 1024];
__device__ float    g_b1r[G4H];
__device__ float    g_b2r[G4H];

// ---------------------------------------------------------------------------
// helpers
// ---------------------------------------------------------------------------
__device__ __forceinline__ float bfr(float a) {
    return __bfloat162float(__float2bfloat16(a));
}
__device__ __forceinline__ uint32_t packbf(float e0, float e1) {
    uint32_t d;
    asm("cvt.rn.bf16x2.f32 %0, %1, %2;" : "=r"(d) : "f"(e1), "f"(e0));
    return d;
}
__device__ __forceinline__ void mma_bf16(float* c, const uint32_t* a,
                                         const uint32_t* b) {
    asm volatile(
        "mma.sync.aligned.m16n8k16.row.col.f32.bf16.bf16.f32 "
        "{%0,%1,%2,%3}, {%4,%5,%6,%7}, {%8,%9}, {%0,%1,%2,%3};"
        : "+f"(c[0]), "+f"(c[1]), "+f"(c[2]), "+f"(c[3])
        : "r"(a[0]), "r"(a[1]), "r"(a[2]), "r"(a[3]), "r"(b[0]), "r"(b[1]));
}

#define CPASYNC16(dst, src) \
    asm volatile("cp.async.ca.shared.global [%0], [%1], 16;" :: "r"(dst), "l"(src))
#define CPASYNC16CG(dst, src) \
    asm volatile("cp.async.cg.shared.global [%0], [%1], 16;" :: "r"(dst), "l"(src))
#define CP_COMMIT() asm volatile("cp.async.commit_group;")
#define CP_WAIT0()  asm volatile("cp.async.wait_group 0;")

__device__ __forceinline__ float fast_sig(float v)  { return 1.0f / (1.0f + __expf(-v)); }
__device__ __forceinline__ float fast_tanh(float v) { return 1.0f - 2.0f / (__expf(2.0f * v) + 1.0f); }

// ---------------------------------------------------------------------------
// Prolog 1: sort rows by length desc (bitonic, deterministic, idx asc ties),
// build perm/lenS and the per-step active-block schedule nbArr.
// key = (200-len)<<11 | idx, ascending sort.
// ---------------------------------------------------------------------------
__global__ void sort_kernel(const int* __restrict__ lengths)
{
    __shared__ unsigned key[Bsz];
    const int tid = threadIdx.x;       // 1024 threads
    key[tid]        = ((unsigned)(200 - lengths[tid]) << 11) | (unsigned)tid;
    key[tid + 1024] = ((unsigned)(200 - lengths[tid + 1024]) << 11)
                      | (unsigned)(tid + 1024);
    __syncthreads();
    for (int k = 2; k <= Bsz; k <<= 1) {
        for (int j = k >> 1; j > 0; j >>= 1) {
            const int i   = ((tid & ~(j - 1)) << 1) | (tid & (j - 1));
            const int par = i | j;
            const bool up = ((i & k) == 0);
            const unsigned a = key[i], b = key[par];
            if (up ? (a > b) : (a < b)) { key[i] = b; key[par] = a; }
            __syncthreads();
        }
    }
    for (int i = tid; i < Bsz; i += 1024) {
        g_perm[i] = (int)(key[i] & 2047u);
        g_lenS[i] = 200 - (int)(key[i] >> 11);
    }
    __syncthreads();
    if (tid < Tlen) {
        // R = #rows with len > tid  <=>  lower_bound of (200-tid)<<11
        const unsigned thr = (unsigned)(200 - tid) << 11;
        int lo = 0, hi = Bsz;
        while (lo < hi) {
            const int mid = (lo + hi) >> 1;
            if (key[mid] < thr) lo = mid + 1; else hi = mid;
        }
        const int cb = (lo + 127) >> 7;            // ceil(R/128)
        int nb = 4;
        while (nb < cb) nb <<= 1;                  // pow2ceil, min 4
        if (nb > 16) nb = 16;
        g_nbArr[tid] = nb;
    }
}

// ---------------------------------------------------------------------------
// Prolog 2: split x into packed bf16x2 hi/lo, permuted into sorted row order.
// ---------------------------------------------------------------------------
__global__ void split_x_kernel(const float* __restrict__ x)
{
    const int n2 = Bsz * (XSTR / 2);   // uint2 elements per dest
    for (int i = blockIdx.x * blockDim.x + threadIdx.x; i < n2;
         i += gridDim.x * blockDim.x) {
        const int srow = i / (XSTR / 2);
        const int rem  = i % (XSTR / 2);
        const int orow = g_perm[srow];
        float4 v = ((const float4*)x)[(size_t)orow * (XSTR / 2) + rem];
        uint2 wh, wl;
        wh.x = packbf(v.x, v.y);
        wh.y = packbf(v.z, v.w);
        wl.x = packbf(v.x - bfr(v.x), v.y - bfr(v.y));
        wl.y = packbf(v.z - bfr(v.z), v.w - bfr(v.w));
        ((uint2*)g_xh)[i] = wh;
        ((uint2*)g_xl)[i] = wl;
    }
}

// ---------------------------------------------------------------------------
// Prolog 3: weight reorder into fragment order + bf16 hi/lo split.
// ---------------------------------------------------------------------------
__global__ void reorder_frag(const float* __restrict__ W,
                             const float* __restrict__ bias,
                             int NC, int which)
{
    uint32_t* Wf = which ? g_W2f : g_W1f;
    float*    bd = which ? g_b2r : g_b1r;
    const int n = 32 * NC * 1024;
    for (int idx = blockIdx.x * blockDim.x + threadIdx.x; idx < n;
         idx += gridDim.x * blockDim.x) {
        int nt   = idx & 3;
        int lane = (idx >> 2) & 31;
        int r    = (idx >> 7) & 1;
        int ks2  = (idx >> 8) & 1;
        int hl   = (idx >> 9) & 1;
        int sc   = idx >> 10;
        int c    = sc % NC;
        int s    = sc / NC;

        int k0  = c * 32 + ks2 * 16 + r * 8 + 2 * (lane & 3);
        int col = s * 32 + nt * 8 + (lane >> 2);
        int h = col >> 2, g = col & 3;
        float w0 = W[k0 * G4H + g * Hdim + h];
        float w1 = W[(k0 + 1) * G4H + g * Hdim + h];
        Wf[idx] = (hl == 0)
            ? packbf(w0, w1)
            : packbf(w0 - bfr(w0), w1 - bfr(w1));

        if (idx < G4H) {
            int hh = idx >> 2, gg = idx & 3;
            bd[idx] = bias[gg * Hdim + hh];
        }
    }
}

__global__ void zero_kernel()
{
    const int idx = blockIdx.x * blockDim.x + threadIdx.x;
    if (idx == 0) g_bar = 0u;
    if (idx < Bsz * Hdim) {
        g_c1[idx] = 0.f; g_c2[idx] = 0.f; g_sum[idx] = 0.f;
    }
    if (idx < Bsz * HW) {
        g_h1h[0][idx] = 0u; g_h1l[0][idx] = 0u;
        g_h2h[0][idx] = 0u; g_h2l[0][idx] = 0u;
        g_h1h[1][idx] = 0u; g_h1l[1][idx] = 0u;
        g_h2h[1][idx] = 0u; g_h2l[1][idx] = 0u;
    }
}

// ---------------------------------------------------------------------------
// One layer phase, templated on LAYER and NB (active row blocks: 16/8/4).
// All 128 CTAs retile over the active prefix: STRIPS = 128/NB CTAs per block,
// each covering 8*NB gate columns. bf16 m16n8k16 3-term split GEMM with
// cp.async double buffer; fused LSTM cell epilogue; c/sum state in gmem
// (.cg, ownership migrates across steps). Rows past their length are simply
// masked (sorted order: once invalid, forever invalid; stale h is finite
// and feeds only masked outputs, so no copy-through is needed).
// ---------------------------------------------------------------------------
#define ASTR   20
#define A_LO_W 2560
#define B_W    5120
#define STGW   9216
#define STGB   (STGW * 4)          // 36864 B
#define SMEM_TOTAL (2 * STGB)      // 73728 B
#define ZSTR   132

template <int LAYER, int NB>
__device__ __forceinline__ void phase_fn(int t)
{
    constexpr int NC   = (LAYER == 1) ? NC1 : NC2;
    constexpr int W0C  = (LAYER == 1) ? 4 : 8;   // chunks from segment 0
    constexpr int NT   = NB / 4;     // n8 tiles per warp
    constexpr int STRN = NB / 4;     // 32-col weight strips per CTA
    constexpr int WPS  = 4 / NT;     // warps sharing one strip
    constexpr int STRIPS = 128 / NB; // CTAs per row block
    constexpr int UPT  = NB / 2;     // units per epilogue thread

    extern __shared__ uint32_t smw[];
    uint32_t smb;
    asm("{ .reg .u64 t0; cvta.to.shared.u64 t0, %1; cvt.u32.u64 %0, t0; }"
        : "=r"(smb) : "l"(smw));

    const uint32_t* __restrict__ Wf = (LAYER == 1) ? g_W1f : g_W2f;
    const float*    __restrict__ bd = (LAYER == 1) ? g_b1r : g_b2r;
    float* __restrict__ cst = (LAYER == 1) ? g_c1 : g_c2;

    const int tid  = threadIdx.x;
    const int lane = tid & 31;
    const int gq   = lane >> 2;
    const int rq   = lane & 3;
    const int wid  = tid >> 5;
    const int wr   = wid & 3;
    const int wcol = wid >> 2;
    const int rb   = blockIdx.x / STRIPS;
    const int cs   = blockIdx.x % STRIPS;
    const int row0 = rb * 128;
    const int col0 = cs * (8 * NB);
    const int sbase = cs * STRN;
    const int prow = tid >> 2;
    const int pq   = tid & 3;
    const int erow = tid >> 2;
    const int eub  = (tid & 3) * UPT;

    const int p = t & 1;
    const uint32_t* s0h; const uint32_t* s0l; size_t s0s, s0k;
    if (LAYER == 1) { s0h = g_xh; s0l = g_xl; s0s = XSTR; s0k = (size_t)t * XW; }
    else            { s0h = g_h1h[p ^ 1]; s0l = g_h1l[p ^ 1]; s0s = HW; s0k = 0; }
    const uint32_t* hph = (LAYER == 1) ? g_h1h[p] : g_h2h[p];
    const uint32_t* hpl = (LAYER == 1) ? g_h1l[p] : g_h2l[p];
    uint32_t* hnh = (LAYER == 1) ? g_h1h[p ^ 1] : g_h2h[p ^ 1];
    uint32_t* hnl = (LAYER == 1) ? g_h1l[p ^ 1] : g_h2l[p ^ 1];

    // ---- epilogue ownership + state prefetch (hidden under GEMM) ----
    const int rowg  = row0 + erow;
    const int mylen = g_lenS[rowg];
    const bool valid = (t < mylen);
    const int gu0 = (col0 >> 2) + eub;
    float creg[UPT], sumr[UPT];
    if (valid) {
#pragma unroll
        for (int u = 0; u < UPT; u++) {
            creg[u] = __ldcg(&cst[rowg * Hdim + gu0 + u]);
            if (LAYER == 2) sumr[u] = __ldcg(&g_sum[rowg * Hdim + gu0 + u]);
        }
    }

    auto fill = [&](int c) {
        const uint32_t sb = smb + (uint32_t)(c & 1) * STGB;
        size_t off; const uint32_t *ph, *pl;
        if (c < W0C) {
            ph = s0h; pl = s0l;
            off = (size_t)(row0 + prow) * s0s + s0k + c * 16 + pq * 4;
        } else {
            ph = hph; pl = hpl;
            off = (size_t)(row0 + prow) * HW + (c - W0C) * 16 + pq * 4;
        }
        const uint32_t adst = sb + (uint32_t)(prow * ASTR + pq * 4) * 4u;
        CPASYNC16CG(adst, ph + off);                 // .cg: no stale L1
        CPASYNC16CG(adst + A_LO_W * 4u, pl + off);
        // B: STRN strips * 1024 words; 16B per op
#pragma unroll
        for (int o = 0; o < (STRN * 256 + 511) / 512; o++) {
            const int oo = tid + o * 512;
            if ((STRN * 256 % 512 == 0) || (oo < STRN * 256)) {
                const int j = oo >> 8;
                const int w = (oo & 255) * 4;
                const uint32_t* src =
                    Wf + ((size_t)(sbase + j) * NC + c) * 1024 + w;
                CPASYNC16(sb + (uint32_t)(B_W + j * 1024 + w) * 4u, src);
            }
        }
    };

    float acc[2][NT][4];
#pragma unroll
    for (int mt = 0; mt < 2; mt++)
#pragma unroll
        for (int nt = 0; nt < NT; nt++)
#pragma unroll
            for (int q = 0; q < 4; q++) acc[mt][nt][q] = 0.0f;

    fill(0);
    CP_COMMIT();

#pragma unroll 1
    for (int c = 0; c < NC; c++) {
        CP_WAIT0();
        __syncthreads();
        if (c + 1 < NC) { fill(c + 1); CP_COMMIT(); }

        const uint32_t* ash = smw + (c & 1) * STGW;
        const uint32_t* asl = ash + A_LO_W;
        const uint32_t* bb  = ash + B_W + (wcol / WPS) * 1024
                            + (wcol % WPS) * NT;

#pragma unroll
        for (int ks2 = 0; ks2 < 2; ks2++) {
            uint32_t bh0[NT], bh1[NT], bl0[NT], bl1[NT];
            if (NT == 4) {
                *(uint4*)bh0 = *(const uint4*)(bb + ks2 * 256 + lane * 4);
                *(uint4*)bh1 = *(const uint4*)(bb + ks2 * 256 + 128 + lane * 4);
                *(uint4*)bl0 = *(const uint4*)(bb + 512 + ks2 * 256 + lane * 4);
                *(uint4*)bl1 = *(const uint4*)(bb + 512 + ks2 * 256 + 128 + lane * 4);
            } else if (NT == 2) {
                *(uint2*)bh0 = *(const uint2*)(bb + ks2 * 256 + lane * 4);
                *(uint2*)bh1 = *(const uint2*)(bb + ks2 * 256 + 128 + lane * 4);
                *(uint2*)bl0 = *(const uint2*)(bb + 512 + ks2 * 256 + lane * 4);
                *(uint2*)bl1 = *(const uint2*)(bb + 512 + ks2 * 256 + 128 + lane * 4);
            } else {
                bh0[0] = bb[ks2 * 256 + lane * 4];
                bh1[0] = bb[ks2 * 256 + 128 + lane * 4];
                bl0[0] = bb[512 + ks2 * 256 + lane * 4];
                bl1[0] = bb[512 + ks2 * 256 + 128 + lane * 4];
            }

            const int kw = ks2 * 8 + rq;
#pragma unroll
            for (int mt = 0; mt < 2; mt++) {
                const int r0 = wr * 32 + mt * 16 + gq;
                uint32_t ah[4], al[4];
                ah[0] = ash[r0 * ASTR + kw];
                ah[1] = ash[(r0 + 8) * ASTR + kw];
                ah[2] = ash[r0 * ASTR + kw + 4];
                ah[3] = ash[(r0 + 8) * ASTR + kw + 4];
                al[0] = asl[r0 * ASTR + kw];
                al[1] = asl[(r0 + 8) * ASTR + kw];
                al[2] = asl[r0 * ASTR + kw + 4];
                al[3] = asl[(r0 + 8) * ASTR + kw + 4];
#pragma unroll
                for (int nt = 0; nt < NT; nt++) {
                    uint32_t bhp[2] = { bh0[nt], bh1[nt] };
                    uint32_t blp[2] = { bl0[nt], bl1[nt] };
                    mma_bf16(acc[mt][nt], ah, bhp);
                    mma_bf16(acc[mt][nt], ah, blp);
                    mma_bf16(acc[mt][nt], al, bhp);
                }
            }
        }
    }
    __syncthreads();   // all compute done before Z overwrites stages

    // ---- stage Z in smem ----
    float* Zs = (float*)smw;
#pragma unroll
    for (int mt = 0; mt < 2; mt++)
#pragma unroll
        for (int nt = 0; nt < NT; nt++) {
            const int row = wr * 32 + mt * 16 + gq;
            const int col = wcol * (8 * NT) + nt * 8 + 2 * rq;
            Zs[row * ZSTR + col]           = acc[mt][nt][0];
            Zs[row * ZSTR + col + 1]       = acc[mt][nt][1];
            Zs[(row + 8) * ZSTR + col]     = acc[mt][nt][2];
            Zs[(row + 8) * ZSTR + col + 1] = acc[mt][nt][3];
        }
    __syncthreads();

    // ---- fused LSTM cell (valid rows only) ----
    if (valid) {
        const size_t hw0 = (size_t)rowg * HW + (gu0 >> 1);
#pragma unroll
        for (int u2 = 0; u2 < UPT / 2; u2++) {
            float nhv[2];
#pragma unroll
            for (int e = 0; e < 2; e++) {
                const int uu = 2 * u2 + e;
                const int n4 = (eub + uu) * 4;
                float4 z  = *(const float4*)&Zs[erow * ZSTR + n4];
                float4 bv = *(const float4*)&bd[col0 + n4];
                const float zi = z.x + bv.x;
                const float zj = z.y + bv.y;
                const float zf = z.z + bv.z;
                const float zo = z.w + bv.w;
                const float nc = creg[uu] * fast_sig(zf + 1.0f)
                               + fast_sig(zi) * fast_tanh(zj);
                const float nh = fast_tanh(nc) * fast_sig(zo);
                creg[uu] = nc;
                if (LAYER == 2) sumr[uu] += nh;
                nhv[e] = nh;
            }
            hnh[hw0 + u2] = packbf(nhv[0], nhv[1]);
            hnl[hw0 + u2] = packbf(nhv[0] - bfr(nhv[0]),
                                   nhv[1] - bfr(nhv[1]));
        }
#pragma unroll
        for (int u = 0; u < UPT; u++) {
            __stcg(&cst[rowg * Hdim + gu0 + u], creg[u]);
            if (LAYER == 2) __stcg(&g_sum[rowg * Hdim + gu0 + u], sumr[u]);
        }
    }
    __syncthreads();   // Z reads done before next phase's fill
}

// ---------------------------------------------------------------------------
// Persistent kernel: 128 CTAs, 200 steps x 2 layers, one global barrier/step.
// ---------------------------------------------------------------------------
__global__ void __launch_bounds__(512, 1)
lstm_persist()
{
    const int tid = threadIdx.x;

#pragma unroll 1
    for (int t = 0; t < Tlen; t++) {
        const int nb = g_nbArr[t];

        if (nb == 16)     phase_fn<1, 16>(t);
        else if (nb == 8) phase_fn<1, 8>(t);
        else              phase_fn<1, 4>(t);

        // global 128-CTA barrier (release/acquire, cumulative)
        if (tid == 0) {
            unsigned* bp = &g_bar;
            asm volatile("red.release.gpu.add.u32 [%0], 1;" :: "l"(bp) : "memory");
            const unsigned tgt = 128u * (unsigned)(t + 1);
            unsigned v;
            while (true) {
                asm volatile("ld.acquire.gpu.b32 %0, [%1];"
                             : "=r"(v) : "l"(bp) : "memory");
                if (v >= tgt) break;
                asm volatile("nanosleep.u32 128;");
            }
        }
        __syncthreads();

        if (nb == 16)     phase_fn<2, 16>(t);
        else if (nb == 8) phase_fn<2, 8>(t);
        else              phase_fn<2, 4>(t);
    }
}

// ---------------------------------------------------------------------------
// logits[orig b, o] = dot(sum_sorted[srow,:], Wout[:,o]) / lenS[srow] + bout[o]
// ---------------------------------------------------------------------------
__global__ void final_kernel(const float* __restrict__ Wout,
                             const float* __restrict__ bout,
                             float* __restrict__ out)
{
    const int idx = blockIdx.x * blockDim.x + threadIdx.x;
    if (idx >= Bsz * Odim) return;
    const int srow = idx / Odim;
    const int o    = idx % Odim;
    const float* s = g_sum + srow * Hdim;
    float acc = 0.0f;
#pragma unroll 8
    for (int h = 0; h < Hdim; h++) acc += s[h] * Wout[h * Odim + o];
    out[g_perm[srow] * Odim + o] =
        acc / (float)g_lenS[srow] + bout[o];
}

// ---------------------------------------------------------------------------
// Inputs (metadata order): x, lengths, W1, b1, W2, b2, Wout, bout
// ---------------------------------------------------------------------------
extern "C" void kernel_launch(void* const* d_in, const int* in_sizes, int n_in,
                              void* d_out, int out_size)
{
    const float* x       = (const float*)d_in[0];
    const int*   lengths = (const int*)d_in[1];
    const float* W1      = (const float*)d_in[2];
    const float* b1      = (const float*)d_in[3];
    const float* W2      = (const float*)d_in[4];
    const float* b2      = (const float*)d_in[5];
    const float* Wout    = (const float*)d_in[6];
    const float* bout    = (const float*)d_in[7];
    float* out = (float*)d_out;

    cudaFuncSetAttribute(lstm_persist,
                         cudaFuncAttributeMaxDynamicSharedMemorySize, SMEM_TOTAL);

    sort_kernel<<<1, 1024>>>(lengths);
    split_x_kernel<<<4096, 256>>>(x);
    reorder_frag<<<1536, 256>>>(W1, b1, NC1, 0);
    reorder_frag<<<2048, 256>>>(W2, b2, NC2, 1);
    zero_kernel<<<2048, 256>>>();

    lstm_persist<<<128, 512, SMEM_TOTAL>>>();

    final_kernel<<<(Bsz * Odim + 255) / 256, 256>>>(Wout, bout, out);
}